// round 14
// baseline (speedup 1.0000x reference)
#include <cuda_runtime.h>
#include <cuda_bf16.h>
#include <math.h>
#include <stdint.h>

#define NATOMS 16384
#define NMOL   512
#define APM    32
#define HDIM   128
#define GDIM   50
#define LINT   3
#define CUTOFF 6.0f
#define TAB_N  2048
#define TILES  8
#define TS     64

// Scratch (allocation-free)
__device__ float g_h  [NATOMS * HDIM];
__device__ float g_hx [NATOMS * HDIM];
__device__ float g_agg[NATOMS * HDIM];
__device__ int   g_ucnt[NMOL];
__device__ unsigned g_upak[NMOL * 512];
__device__ int   g_ioff[NMOL * TILES * 33];
__device__ int   g_joff[NMOL * TILES * 33];
__device__ int   g_jperm[NMOL * 512];
__device__ float g_wtab[LINT * (TAB_N + 1) * HDIM];

__device__ __forceinline__ float sspf(float x) {
    const float LN2 = 0.6931471805599453f;
    if (x > 20.f) return x - LN2;
    return __logf(1.f + __expf(x)) - LN2;
}
__device__ __forceinline__ void split2(float v0, float v1, uint32_t& hi, uint32_t& lo) {
    __nv_bfloat16 h0 = __float2bfloat16(v0), h1 = __float2bfloat16(v1);
    __nv_bfloat16 l0 = __float2bfloat16(v0 - __bfloat162float(h0));
    __nv_bfloat16 l1 = __float2bfloat16(v1 - __bfloat162float(h1));
    hi = (uint32_t)__bfloat16_as_ushort(h0) | ((uint32_t)__bfloat16_as_ushort(h1) << 16);
    lo = (uint32_t)__bfloat16_as_ushort(l0) | ((uint32_t)__bfloat16_as_ushort(l1) << 16);
}
__device__ __forceinline__ void mma16816(float* d,
    uint32_t a0, uint32_t a1, uint32_t a2, uint32_t a3, uint32_t b0, uint32_t b1) {
    asm volatile(
        "mma.sync.aligned.m16n8k16.row.col.f32.bf16.bf16.f32 "
        "{%0,%1,%2,%3}, {%4,%5,%6,%7}, {%8,%9}, {%0,%1,%2,%3};"
        : "+f"(d[0]), "+f"(d[1]), "+f"(d[2]), "+f"(d[3])
        : "r"(a0), "r"(a1), "r"(a2), "r"(a3), "r"(b0), "r"(b1));
}
__device__ __forceinline__ void eaf(float d, float gofs, float step, float coeff,
                                    uint32_t& hi, uint32_t& lo) {
    float u0 = d - gofs, u1 = d - gofs - step;
    float e0 = __expf(coeff * u0 * u0);
    float e1 = __expf(coeff * u1 * u1);
    split2(e0, e1, hi, lo);
}

// ---------------------------------------------------------------------------
// Prepass with fused moff (unchanged)
// ---------------------------------------------------------------------------
__global__ __launch_bounds__(128) void k_prep(const int* __restrict__ src,
                                              const int* __restrict__ dst, int E) {
    __shared__ unsigned spak[TS];
    __shared__ int scnt2[33];
    __shared__ int snu;
    __shared__ int sbounds[2];
    int m = blockIdx.x;
    int tid = threadIdx.x, lane = tid & 31, wid = tid >> 5;

    if (tid < 2) {
        int target = (m + tid) * APM;
        int lo = 0, hi = E;
        while (lo < hi) { int mid = (lo + hi) >> 1; if (src[mid] < target) lo = mid + 1; else hi = mid; }
        sbounds[tid] = lo;
    }
    __syncthreads();
    int e0 = sbounds[0], e1 = sbounds[1];

    if (wid == 0) {
        int cnt = 0;
        for (int base = e0; base < e1; base += 32) {
            int e = base + lane;
            bool p = false; unsigned pk = 0;
            if (e < e1) {
                int s = src[e] - m * APM, d2 = dst[e] - m * APM;
                if (d2 > s) { p = true; pk = (unsigned)((s << 8) | d2); }
            }
            unsigned msk = __ballot_sync(0xffffffffu, p);
            if (p) g_upak[m * 512 + cnt + __popc(msk & ((1u << lane) - 1))] = pk;
            cnt += __popc(msk);
        }
        if (lane == 0) { g_ucnt[m] = cnt; snu = cnt; }
    }
    __syncthreads();
    int nu = snu;
    int nt = (nu + TS - 1) / TS;

    for (int t = 0; t < nt; t++) {
        int nr = nu - t * TS; if (nr > TS) nr = TS;
        if (tid < TS) spak[tid] = (tid < nr) ? g_upak[m * 512 + t * TS + tid] : 0xffffffffu;
        __syncthreads();
        if (wid == 0) {
            int a = lane, c = 0;
            for (int r = 0; r < nr; r++) c += ((int)(spak[r] >> 8) < a) ? 1 : 0;
            g_ioff[(m * TILES + t) * 33 + a] = c;
            if (lane == 0) g_ioff[(m * TILES + t) * 33 + 32] = nr;
        }
        if (wid == 1) {
            int a = lane, c = 0;
            for (int r = 0; r < nr; r++) c += ((int)(spak[r] & 255) == a) ? 1 : 0;
            int x = c;
            #pragma unroll
            for (int o = 1; o < 32; o <<= 1) {
                int y = __shfl_up_sync(0xffffffffu, x, o);
                if (lane >= o) x += y;
            }
            int excl = x - c;
            g_joff[(m * TILES + t) * 33 + a] = excl;
            scnt2[a] = excl;
            if (lane == 31) g_joff[(m * TILES + t) * 33 + 32] = excl + c;
        }
        __syncthreads();
        if (tid == 0) {
            for (int r = 0; r < nr; r++) {
                int j = (int)(spak[r] & 255);
                g_jperm[m * 512 + t * TS + scnt2[j]] = r;
                scnt2[j]++;
            }
        }
        __syncthreads();
    }
}

// ---------------------------------------------------------------------------
// Fused embed + node GEMM (unchanged)
// ---------------------------------------------------------------------------
#define N1_SMEM (128 * 132 * 4)

__global__ __launch_bounds__(512, 1) void k_n1e(
    const int* __restrict__ z, const float* __restrict__ emb,
    const float* __restrict__ W, float* __restrict__ h, float* __restrict__ hx)
{
    extern __shared__ uint32_t smu[];
    uint32_t* Bu = smu;
    const int tid = threadIdx.x, wid = tid >> 5, lane = tid & 31;
    const int half = wid >> 3, w8 = wid & 7;
    const int qr = lane >> 2, qc = lane & 3;

    for (int i = tid; i < 128 * 64; i += 512) {
        int kp = i >> 7, n = i & 127;
        uint32_t hh, ll;
        split2(W[(2 * kp) * 128 + n], W[(2 * kp + 1) * 128 + n], hh, ll);
        Bu[n * 132 + kp] = hh;
        Bu[n * 132 + 64 + kp] = ll;
    }
    __syncthreads();

    const int r0 = w8 * 16 + qr;
    const long base = (long)blockIdx.x * 128;
    const long za = (long)z[base + r0], zb = (long)z[base + r0 + 8];

    float acc[8][4];
    #pragma unroll
    for (int nb = 0; nb < 8; nb++) { acc[nb][0]=0.f; acc[nb][1]=0.f; acc[nb][2]=0.f; acc[nb][3]=0.f; }

    #pragma unroll
    for (int ks = 0; ks < 8; ks++) {
        const float* xr0 = emb + za * 128 + ks * 16 + 2 * qc;
        const float* xr1 = emb + zb * 128 + ks * 16 + 2 * qc;
        float2 v00 = *(const float2*)xr0;
        float2 v01 = *(const float2*)(xr0 + 8);
        float2 v10 = *(const float2*)xr1;
        float2 v11 = *(const float2*)(xr1 + 8);
        if (half == 0) {
            *(float2*)(h + (base + r0) * 128 + ks * 16 + 2 * qc)         = v00;
            *(float2*)(h + (base + r0) * 128 + ks * 16 + 8 + 2 * qc)     = v01;
            *(float2*)(h + (base + r0 + 8) * 128 + ks * 16 + 2 * qc)     = v10;
            *(float2*)(h + (base + r0 + 8) * 128 + ks * 16 + 8 + 2 * qc) = v11;
        }
        uint32_t aH0,aH1,aH2,aH3,aL0,aL1,aL2,aL3;
        split2(v00.x, v00.y, aH0, aL0);
        split2(v10.x, v10.y, aH1, aL1);
        split2(v01.x, v01.y, aH2, aL2);
        split2(v11.x, v11.y, aH3, aL3);
        #pragma unroll
        for (int nb = 0; nb < 8; nb++) {
            int noff = ((half * 8 + nb) * 8 + qr) * 132 + ks * 8 + qc;
            uint32_t bh0 = Bu[noff], bh1 = Bu[noff + 4];
            mma16816(acc[nb], aH0, aH1, aH2, aH3, bh0, bh1);
            mma16816(acc[nb], aL0, aL1, aL2, aL3, bh0, bh1);
            uint32_t bl0 = Bu[noff + 64], bl1 = Bu[noff + 68];
            mma16816(acc[nb], aH0, aH1, aH2, aH3, bl0, bl1);
        }
    }

    #pragma unroll
    for (int nb = 0; nb < 8; nb++) {
        int c = (half * 8 + nb) * 8 + 2 * qc;
        *(float2*)(hx + (base + r0) * 128 + c)     = make_float2(acc[nb][0], acc[nb][1]);
        *(float2*)(hx + (base + r0 + 8) * 128 + c) = make_float2(acc[nb][2], acc[nb][3]);
    }
}

// ---------------------------------------------------------------------------
// Fused node chain + output head (staging re-phased for latency)
// ---------------------------------------------------------------------------
#define N2_OB1 0
#define N2_OB2 16896
#define N2_OT1 33792
#define N2_OS2 50688
#define N2_OSL 50816
#define N2_OSA 50944
#define N2_SMEM ((51072) * 4)

__global__ __launch_bounds__(512, 1) void k_n2x(
    const float* __restrict__ agg,
    const float* __restrict__ W2, const float* __restrict__ b2,
    const float* __restrict__ Wl, const float* __restrict__ lb,
    float* __restrict__ h,
    const float* __restrict__ cf1n, float* __restrict__ hx,
    const float* __restrict__ o1w, const float* __restrict__ o1b,
    const float* __restrict__ o2w, const float* __restrict__ o2b,
    float* __restrict__ out)
{
    extern __shared__ uint32_t smu[];
    uint32_t* Bu1 = smu + N2_OB1;
    uint32_t* Bu2 = smu + N2_OB2;
    uint32_t* T1  = smu + N2_OT1;
    float* sb2 = (float*)(smu + N2_OS2);
    float* slb = (float*)(smu + N2_OSL);
    float* satom = (float*)(smu + N2_OSA);

    const int tid = threadIdx.x, wid = tid >> 5, lane = tid & 31;
    const int half = wid >> 3, w8 = wid & 7;
    const int qr = lane >> 2, qc = lane & 3;

    // Stage only what GEMM1 needs (Bu1 = W2 split) + biases
    for (int i = tid; i < 128 * 64; i += 512) {
        int kp = i >> 7, n = i & 127;
        uint32_t hh, ll;
        split2(W2[(2 * kp) * 128 + n], W2[(2 * kp + 1) * 128 + n], hh, ll);
        Bu1[n * 132 + kp] = hh; Bu1[n * 132 + 64 + kp] = ll;
    }
    if (tid < 128) { sb2[tid] = b2[tid]; slb[tid] = lb[tid]; }
    __syncthreads();

    const int r0 = w8 * 16 + qr;
    const long base = (long)blockIdx.x * 128;

    // GEMM1: agg @ W2 -> ssp -> T1
    {
        float acc[8][4];
        #pragma unroll
        for (int nb = 0; nb < 8; nb++) { acc[nb][0]=0.f; acc[nb][1]=0.f; acc[nb][2]=0.f; acc[nb][3]=0.f; }
        #pragma unroll
        for (int ks = 0; ks < 8; ks++) {
            const float* xr = agg + (base + r0) * 128 + ks * 16 + 2 * qc;
            float2 v00 = *(const float2*)xr;
            float2 v01 = *(const float2*)(xr + 8);
            float2 v10 = *(const float2*)(xr + 8 * 128);
            float2 v11 = *(const float2*)(xr + 8 * 128 + 8);
            uint32_t aH0,aH1,aH2,aH3,aL0,aL1,aL2,aL3;
            split2(v00.x, v00.y, aH0, aL0);
            split2(v10.x, v10.y, aH1, aL1);
            split2(v01.x, v01.y, aH2, aL2);
            split2(v11.x, v11.y, aH3, aL3);
            #pragma unroll
            for (int nb = 0; nb < 8; nb++) {
                int noff = ((half * 8 + nb) * 8 + qr) * 132 + ks * 8 + qc;
                uint32_t bh0 = Bu1[noff], bh1 = Bu1[noff + 4];
                mma16816(acc[nb], aH0, aH1, aH2, aH3, bh0, bh1);
                mma16816(acc[nb], aL0, aL1, aL2, aL3, bh0, bh1);
                uint32_t bl0 = Bu1[noff + 64], bl1 = Bu1[noff + 68];
                mma16816(acc[nb], aH0, aH1, aH2, aH3, bl0, bl1);
            }
        }
        #pragma unroll
        for (int nb = 0; nb < 8; nb++) {
            int c = (half * 8 + nb) * 8 + 2 * qc;
            int kp = (c >> 1);
            float bx = sb2[c], by = sb2[c + 1];
            uint32_t hh, ll;
            split2(sspf(acc[nb][0] + bx), sspf(acc[nb][1] + by), hh, ll);
            T1[r0 * 132 + kp] = hh; T1[r0 * 132 + 64 + kp] = ll;
            split2(sspf(acc[nb][2] + bx), sspf(acc[nb][3] + by), hh, ll);
            T1[(r0 + 8) * 132 + kp] = hh; T1[(r0 + 8) * 132 + 64 + kp] = ll;
        }
    }
    // Stage Bu2 (Wl) now; covered by the sync below
    for (int i = tid; i < 128 * 64; i += 512) {
        int kp = i >> 7, n = i & 127;
        uint32_t hh, ll;
        split2(Wl[(2 * kp) * 128 + n], Wl[(2 * kp + 1) * 128 + n], hh, ll);
        Bu2[n * 132 + kp] = hh; Bu2[n * 132 + 64 + kp] = ll;
    }
    __syncthreads();

    // GEMM2: T1 @ Wl, residual -> h; re-split h_new into T1
    {
        float acc[8][4];
        #pragma unroll
        for (int nb = 0; nb < 8; nb++) { acc[nb][0]=0.f; acc[nb][1]=0.f; acc[nb][2]=0.f; acc[nb][3]=0.f; }
        #pragma unroll
        for (int ks = 0; ks < 8; ks++) {
            int xo0 = r0 * 132 + ks * 8 + qc;
            int xo1 = (r0 + 8) * 132 + ks * 8 + qc;
            uint32_t aH0 = T1[xo0],      aH1 = T1[xo1];
            uint32_t aH2 = T1[xo0 + 4],  aH3 = T1[xo1 + 4];
            uint32_t aL0 = T1[xo0 + 64], aL1 = T1[xo1 + 64];
            uint32_t aL2 = T1[xo0 + 68], aL3 = T1[xo1 + 68];
            #pragma unroll
            for (int nb = 0; nb < 8; nb++) {
                int noff = ((half * 8 + nb) * 8 + qr) * 132 + ks * 8 + qc;
                uint32_t bh0 = Bu2[noff], bh1 = Bu2[noff + 4];
                mma16816(acc[nb], aH0, aH1, aH2, aH3, bh0, bh1);
                mma16816(acc[nb], aL0, aL1, aL2, aL3, bh0, bh1);
                uint32_t bl0 = Bu2[noff + 64], bl1 = Bu2[noff + 68];
                mma16816(acc[nb], aH0, aH1, aH2, aH3, bl0, bl1);
            }
        }
        #pragma unroll
        for (int nb = 0; nb < 8; nb++) {
            int c = (half * 8 + nb) * 8 + 2 * qc;
            float bx = slb[c], by = slb[c + 1];
            float* y0 = h + (base + r0) * 128 + c;
            float* y1 = h + (base + r0 + 8) * 128 + c;
            float2 p0 = *(float2*)y0, p1 = *(float2*)y1;
            float v0 = p0.x + acc[nb][0] + bx, v1 = p0.y + acc[nb][1] + by;
            float v2 = p1.x + acc[nb][2] + bx, v3 = p1.y + acc[nb][3] + by;
            *(float2*)y0 = make_float2(v0, v1);
            *(float2*)y1 = make_float2(v2, v3);
            int kp = c >> 1;
            uint32_t hh, ll;
            split2(v0, v1, hh, ll);
            T1[r0 * 132 + kp] = hh; T1[r0 * 132 + 64 + kp] = ll;
            split2(v2, v3, hh, ll);
            T1[(r0 + 8) * 132 + kp] = hh; T1[(r0 + 8) * 132 + 64 + kp] = ll;
        }
    }
    // Stage next weights into Bu1 (no reader until after the sync below)
    if (cf1n) {
        for (int i = tid; i < 128 * 64; i += 512) {
            int kp = i >> 7, n = i & 127;
            uint32_t hh, ll;
            split2(cf1n[(2 * kp) * 128 + n], cf1n[(2 * kp + 1) * 128 + n], hh, ll);
            Bu1[n * 132 + kp] = hh; Bu1[n * 132 + 64 + kp] = ll;
        }
    } else {
        for (int i = tid; i < 64 * 64; i += 512) {
            int kp = i >> 6, n = i & 63;
            uint32_t hh, ll;
            split2(o1w[(2 * kp) * 64 + n], o1w[(2 * kp + 1) * 64 + n], hh, ll);
            Bu1[n * 132 + kp] = hh; Bu1[n * 132 + 64 + kp] = ll;
        }
        if (tid < 64) { sb2[tid] = o1b[tid]; slb[tid] = o2w[tid]; }
        if (tid < 128) satom[tid] = 0.f;
    }
    __syncthreads();   // T1 (h_new split) + staged weights visible

    if (cf1n) {
        // GEMM3: hx = h_new @ cf1n
        float acc[8][4];
        #pragma unroll
        for (int nb = 0; nb < 8; nb++) { acc[nb][0]=0.f; acc[nb][1]=0.f; acc[nb][2]=0.f; acc[nb][3]=0.f; }
        #pragma unroll
        for (int ks = 0; ks < 8; ks++) {
            int xo0 = r0 * 132 + ks * 8 + qc;
            int xo1 = (r0 + 8) * 132 + ks * 8 + qc;
            uint32_t aH0 = T1[xo0],      aH1 = T1[xo1];
            uint32_t aH2 = T1[xo0 + 4],  aH3 = T1[xo1 + 4];
            uint32_t aL0 = T1[xo0 + 64], aL1 = T1[xo1 + 64];
            uint32_t aL2 = T1[xo0 + 68], aL3 = T1[xo1 + 68];
            #pragma unroll
            for (int nb = 0; nb < 8; nb++) {
                int noff = ((half * 8 + nb) * 8 + qr) * 132 + ks * 8 + qc;
                uint32_t bh0 = Bu1[noff], bh1 = Bu1[noff + 4];
                mma16816(acc[nb], aH0, aH1, aH2, aH3, bh0, bh1);
                mma16816(acc[nb], aL0, aL1, aL2, aL3, bh0, bh1);
                uint32_t bl0 = Bu1[noff + 64], bl1 = Bu1[noff + 68];
                mma16816(acc[nb], aH0, aH1, aH2, aH3, bl0, bl1);
            }
        }
        #pragma unroll
        for (int nb = 0; nb < 8; nb++) {
            int c = (half * 8 + nb) * 8 + 2 * qc;
            *(float2*)(hx + (base + r0) * 128 + c)     = make_float2(acc[nb][0], acc[nb][1]);
            *(float2*)(hx + (base + r0 + 8) * 128 + c) = make_float2(acc[nb][2], acc[nb][3]);
        }
        return;
    }

    // ---- Fused output head (last layer) ----
    {
        float acc[4][4];
        #pragma unroll
        for (int nb = 0; nb < 4; nb++) { acc[nb][0]=0.f; acc[nb][1]=0.f; acc[nb][2]=0.f; acc[nb][3]=0.f; }
        #pragma unroll
        for (int ks = 0; ks < 8; ks++) {
            int xo0 = r0 * 132 + ks * 8 + qc;
            int xo1 = (r0 + 8) * 132 + ks * 8 + qc;
            uint32_t aH0 = T1[xo0],      aH1 = T1[xo1];
            uint32_t aH2 = T1[xo0 + 4],  aH3 = T1[xo1 + 4];
            uint32_t aL0 = T1[xo0 + 64], aL1 = T1[xo1 + 64];
            uint32_t aL2 = T1[xo0 + 68], aL3 = T1[xo1 + 68];
            #pragma unroll
            for (int nb = 0; nb < 4; nb++) {
                int cb2 = half * 4 + nb;
                int noff = (cb2 * 8 + qr) * 132 + ks * 8 + qc;
                uint32_t bh0 = Bu1[noff], bh1 = Bu1[noff + 4];
                mma16816(acc[nb], aH0, aH1, aH2, aH3, bh0, bh1);
                mma16816(acc[nb], aL0, aL1, aL2, aL3, bh0, bh1);
                uint32_t bl0 = Bu1[noff + 64], bl1 = Bu1[noff + 68];
                mma16816(acc[nb], aH0, aH1, aH2, aH3, bl0, bl1);
            }
        }
        float P0 = 0.f, P1 = 0.f;
        #pragma unroll
        for (int nb = 0; nb < 4; nb++) {
            int c = (half * 4 + nb) * 8 + 2 * qc;
            float bx = sb2[c], by = sb2[c + 1];
            float wx = slb[c], wy = slb[c + 1];
            P0 += sspf(acc[nb][0] + bx) * wx + sspf(acc[nb][1] + by) * wy;
            P1 += sspf(acc[nb][2] + bx) * wx + sspf(acc[nb][3] + by) * wy;
        }
        atomicAdd(&satom[r0], P0);
        atomicAdd(&satom[r0 + 8], P1);
    }
    __syncthreads();

    if (tid < 4) {
        float s = 0.f;
        #pragma unroll
        for (int a = 0; a < 32; a++) s += satom[tid * 32 + a];
        out[blockIdx.x * 4 + tid] = s + 32.f * o2b[0];
    }
}

// ---------------------------------------------------------------------------
// Table builder, N-split (unchanged)
// ---------------------------------------------------------------------------
#define BLD_SMEM (34304 * 4)

__global__ __launch_bounds__(512, 1)
void k_build(const float* __restrict__ w1all, const float* __restrict__ b1all,
             const float* __restrict__ w2all, const float* __restrict__ b2all)
{
    extern __shared__ uint32_t smu[];
    uint32_t* B1u = smu;
    uint32_t* B2u = smu + 8704;
    uint32_t* T1  = smu + 17152;
    float* sb1 = (float*)(smu + 34048);
    float* sb2 = (float*)(smu + 34176);

    const int tpl = TAB_N / 128;
    const int ch = blockIdx.x & 1;
    const int t  = (blockIdx.x >> 1) % tpl;
    const int l  = (blockIdx.x >> 1) / tpl;
    const float* w1 = w1all + (long)l * GDIM * HDIM;
    const float* b1 = b1all + (long)l * HDIM;
    const float* w2 = w2all + (long)l * HDIM * HDIM;
    const float* b2 = b2all + (long)l * HDIM;

    const int tid = threadIdx.x, wid = tid >> 5, lane = tid & 31;
    const int half = wid >> 3, w8 = wid & 7;
    const int qr = lane >> 2, qc = lane & 3;

    for (int i = tid; i < 128 * 32; i += 512) {
        int kp = i >> 7, n = i & 127, k = 2 * kp;
        float v0 = (k < GDIM)     ? w1[k * 128 + n]       : 0.f;
        float v1 = (k + 1 < GDIM) ? w1[(k + 1) * 128 + n] : 0.f;
        uint32_t h, lv; split2(v0, v1, h, lv);
        B1u[n * 68 + kp] = h;
        B1u[n * 68 + 32 + kp] = lv;
    }
    for (int i = tid; i < 64 * 64; i += 512) {
        int kp = i >> 6, nl = i & 63;
        int n = ch * 64 + nl;
        uint32_t h, lv;
        split2(w2[(2 * kp) * 128 + n], w2[(2 * kp + 1) * 128 + n], h, lv);
        B2u[nl * 132 + kp] = h;
        B2u[nl * 132 + 64 + kp] = lv;
    }
    if (tid < 128) { sb1[tid] = b1[tid]; sb2[tid] = b2[tid]; }
    __syncthreads();

    const float step  = CUTOFF / (GDIM - 1);
    const float coeff = -0.5f / (step * step);
    const float PIOC  = 3.14159265358979f / CUTOFF;
    const float DELTA = CUTOFF / (float)TAB_N;
    const int r0 = w8 * 16 + qr;

    float dv0 = (float)(t * 128 + r0) * DELTA;
    float dv1 = (float)(t * 128 + r0 + 8) * DELTA;

    uint32_t aH[4][4], aL[4][4];
    #pragma unroll
    for (int ks = 0; ks < 4; ks++) {
        float g0 = (float)(ks * 16 + 2 * qc) * step;
        eaf(dv0, g0,            step, coeff, aH[ks][0], aL[ks][0]);
        eaf(dv1, g0,            step, coeff, aH[ks][1], aL[ks][1]);
        eaf(dv0, g0 + 8.f*step, step, coeff, aH[ks][2], aL[ks][2]);
        eaf(dv1, g0 + 8.f*step, step, coeff, aH[ks][3], aL[ks][3]);
    }

    #pragma unroll
    for (int nb = 0; nb < 8; nb++) {
        float acc[4] = {0.f, 0.f, 0.f, 0.f};
        #pragma unroll
        for (int ks = 0; ks < 4; ks++) {
            int noff = ((half * 8 + nb) * 8 + qr) * 68 + ks * 8 + qc;
            uint32_t bh0 = B1u[noff], bh1 = B1u[noff + 4];
            mma16816(acc, aH[ks][0], aH[ks][1], aH[ks][2], aH[ks][3], bh0, bh1);
            mma16816(acc, aL[ks][0], aL[ks][1], aL[ks][2], aL[ks][3], bh0, bh1);
            uint32_t bl0 = B1u[noff + 32], bl1 = B1u[noff + 36];
            mma16816(acc, aH[ks][0], aH[ks][1], aH[ks][2], aH[ks][3], bl0, bl1);
        }
        int c = (half * 8 + nb) * 8 + 2 * qc;
        int kp = c >> 1;
        float bx = sb1[c], by = sb1[c + 1];
        uint32_t hh, ll;
        split2(sspf(acc[0] + bx), sspf(acc[1] + by), hh, ll);
        T1[r0 * 132 + kp] = hh; T1[r0 * 132 + 64 + kp] = ll;
        split2(sspf(acc[2] + bx), sspf(acc[3] + by), hh, ll);
        T1[(r0 + 8) * 132 + kp] = hh; T1[(r0 + 8) * 132 + 64 + kp] = ll;
    }
    __syncthreads();

    float acc2[4][4];
    #pragma unroll
    for (int nb = 0; nb < 4; nb++) { acc2[nb][0]=0.f; acc2[nb][1]=0.f; acc2[nb][2]=0.f; acc2[nb][3]=0.f; }
    #pragma unroll
    for (int ks = 0; ks < 8; ks++) {
        int xo0 = r0 * 132 + ks * 8 + qc;
        int xo1 = (r0 + 8) * 132 + ks * 8 + qc;
        uint32_t aH0 = T1[xo0],      aH1 = T1[xo1];
        uint32_t aH2 = T1[xo0 + 4],  aH3 = T1[xo1 + 4];
        uint32_t aL0 = T1[xo0 + 64], aL1 = T1[xo1 + 64];
        uint32_t aL2 = T1[xo0 + 68], aL3 = T1[xo1 + 68];
        #pragma unroll
        for (int nb = 0; nb < 4; nb++) {
            int cb2 = half * 4 + nb;
            int noff = (cb2 * 8 + qr) * 132 + ks * 8 + qc;
            uint32_t bh0 = B2u[noff], bh1 = B2u[noff + 4];
            mma16816(acc2[nb], aH0, aH1, aH2, aH3, bh0, bh1);
            mma16816(acc2[nb], aL0, aL1, aL2, aL3, bh0, bh1);
            uint32_t bl0 = B2u[noff + 64], bl1 = B2u[noff + 68];
            mma16816(acc2[nb], aH0, aH1, aH2, aH3, bl0, bl1);
        }
    }

    float cc0 = 0.5f * (cosf(dv0 * PIOC) + 1.f);
    float cc1 = 0.5f * (cosf(dv1 * PIOC) + 1.f);
    float* trow = g_wtab + ((long)l * (TAB_N + 1) + t * 128 + r0) * 128;
    #pragma unroll
    for (int nb = 0; nb < 4; nb++) {
        int c = ch * 64 + (half * 4 + nb) * 8 + 2 * qc;
        float bx = sb2[c], by = sb2[c + 1];
        *(float2*)(trow + c) =
            make_float2((acc2[nb][0] + bx) * cc0, (acc2[nb][1] + by) * cc0);
        *(float2*)(trow + 8 * 128 + c) =
            make_float2((acc2[nb][2] + bx) * cc1, (acc2[nb][3] + by) * cc1);
    }
    if (t == 0 && ch == 0 && tid < 128)
        g_wtab[((long)l * (TAB_N + 1) + TAB_N) * 128 + tid] = 0.f;
}

// ---------------------------------------------------------------------------
// Column-split table-lookup edge kernel, 2 syncs/tile (fill computes d inline)
// ---------------------------------------------------------------------------
#define E2_HX 0
#define E2_SB 2176
#define E2_IL 6528
#define E2_JL 6592
#define E2_JP 6656
#define E2_IO 6720
#define E2_JO 6753
#define E2_PS 6786
#define E2_W  6882
#define ETAB_SMEM (E2_W * 4)

__global__ __launch_bounds__(256, 6)
void k_edge_tab(const float* __restrict__ pos, const float* __restrict__ wtab)
{
    extern __shared__ float sm[];
    float* hxs  = sm + E2_HX;     // 32 x 68
    float* sbuf = sm + E2_SB;     // 64 x 68
    int*   sil  = (int*)(sm + E2_IL);
    int*   sjl  = (int*)(sm + E2_JL);
    int*   sjp  = (int*)(sm + E2_JP);
    int*   siof = (int*)(sm + E2_IO);
    int*   sjof = (int*)(sm + E2_JO);
    float* ps   = sm + E2_PS;

    const int tid = threadIdx.x, wid = tid >> 5, lane = tid & 31;
    const int m = blockIdx.x >> 1, ch = blockIdx.x & 1;
    const int cb = ch * 64;
    const int a_own = tid >> 3, c_own = (tid & 7) * 8;
    const float SCALE = (float)TAB_N / CUTOFF;

    int nu = g_ucnt[m];
    int nt = (nu + TS - 1) / TS;

    for (int i = tid; i < APM * 64; i += 256) {
        int a = i >> 6, c = i & 63;
        hxs[a * 68 + c] = g_hx[(long)(m * APM + a) * 128 + cb + c];
    }
    if (tid < 96) ps[tid] = pos[m * 96 + tid];
    float4 agg0 = make_float4(0,0,0,0), agg1 = agg0;
    __syncthreads();

    for (int t = 0; t < nt; t++) {
        int tb = t * TS;
        int nr = nu - tb; if (nr > TS) nr = TS;

        // Phase A: metadata + fill (one phase, one sync)
        if (tid < TS) {
            int k = tb + tid;
            int il = 0, jl = 0;
            if (k < nu) {
                unsigned pk = g_upak[m * 512 + k];
                il = (int)(pk >> 8); jl = (int)(pk & 255);
            }
            sil[tid] = il; sjl[tid] = jl;
            sjp[tid] = g_jperm[m * 512 + tb + tid];
        }
        if (tid >= 64 && tid < 97)   siof[tid - 64]  = g_ioff[(m * TILES + t) * 33 + tid - 64];
        if (tid >= 128 && tid < 161) sjof[tid - 128] = g_joff[(m * TILES + t) * 33 + tid - 128];

        #pragma unroll
        for (int it = 0; it < 4; it++) {
            int e = wid * 8 + it * 2 + (lane >> 4);
            int col4 = lane & 15;
            if (e < nr) {
                unsigned pk = g_upak[m * 512 + tb + e];
                int il = (int)(pk >> 8), jl = (int)(pk & 255);
                float dx = ps[3*il]   - ps[3*jl];
                float dy = ps[3*il+1] - ps[3*jl+1];
                float dz = ps[3*il+2] - ps[3*jl+2];
                float d = sqrtf(dx*dx + dy*dy + dz*dz);
                float tt = d * SCALE;
                int i0 = (int)tt;
                i0 = (i0 > TAB_N - 1) ? (TAB_N - 1) : i0;
                float f = tt - (float)i0;
                const float4* T0 = (const float4*)(wtab + (long)i0 * 128 + cb);
                float4 wa = T0[col4];
                float4 wb = T0[32 + col4];
                float4 wv;
                wv.x = wa.x + f * (wb.x - wa.x);
                wv.y = wa.y + f * (wb.y - wa.y);
                wv.z = wa.z + f * (wb.z - wa.z);
                wv.w = wa.w + f * (wb.w - wa.w);
                *(float4*)&sbuf[e * 68 + col4 * 4] = wv;
            }
        }
        __syncthreads();

        // Phase B: both-direction segmented reduction
        for (int r = siof[a_own]; r < siof[a_own + 1]; r++) {
            const float4* wp = (const float4*)&sbuf[r * 68 + c_own];
            const float4* hp = (const float4*)&hxs[sjl[r] * 68 + c_own];
            float4 w0 = wp[0], w1v = wp[1];
            float4 h0 = hp[0], h1 = hp[1];
            agg0.x += w0.x*h0.x; agg0.y += w0.y*h0.y; agg0.z += w0.z*h0.z; agg0.w += w0.w*h0.w;
            agg1.x += w1v.x*h1.x; agg1.y += w1v.y*h1.y; agg1.z += w1v.z*h1.z; agg1.w += w1v.w*h1.w;
        }
        for (int kk = sjof[a_own]; kk < sjof[a_own + 1]; kk++) {
            int r = sjp[kk];
            const float4* wp = (const float4*)&sbuf[r * 68 + c_own];
            const float4* hp = (const float4*)&hxs[sil[r] * 68 + c_own];
            float4 w0 = wp[0], w1v = wp[1];
            float4 h0 = hp[0], h1 = hp[1];
            agg0.x += w0.x*h0.x; agg0.y += w0.y*h0.y; agg0.z += w0.z*h0.z; agg0.w += w0.w*h0.w;
            agg1.x += w1v.x*h1.x; agg1.y += w1v.y*h1.y; agg1.z += w1v.z*h1.z; agg1.w += w1v.w*h1.w;
        }
        __syncthreads();
    }

    float* ap = g_agg + (long)(m * APM + a_own) * 128 + cb + c_own;
    ((float4*)ap)[0] = agg0;
    ((float4*)ap)[1] = agg1;
}

// ---------------------------------------------------------------------------
extern "C" void kernel_launch(void* const* d_in, const int* in_sizes, int n_in,
                              void* d_out, int out_size)
{
    const int*   z       = (const int*)  d_in[0];
    const float* pos     = (const float*)d_in[1];
    const int*   ei      = (const int*)  d_in[3];
    const float* emb     = (const float*)d_in[4];
    const float* mlp_w1  = (const float*)d_in[5];
    const float* mlp_b1  = (const float*)d_in[6];
    const float* mlp_w2  = (const float*)d_in[7];
    const float* mlp_b2  = (const float*)d_in[8];
    const float* cf1_w   = (const float*)d_in[9];
    const float* cf2_w   = (const float*)d_in[10];
    const float* cf2_b   = (const float*)d_in[11];
    const float* lin_w   = (const float*)d_in[12];
    const float* lin_b   = (const float*)d_in[13];
    const float* out1_w  = (const float*)d_in[14];
    const float* out1_b  = (const float*)d_in[15];
    const float* out2_w  = (const float*)d_in[16];
    const float* out2_b  = (const float*)d_in[17];

    int E = in_sizes[3] / 2;
    const int* src = ei;
    const int* dst = ei + E;

    cudaFuncSetAttribute(k_build, cudaFuncAttributeMaxDynamicSharedMemorySize, BLD_SMEM);
    cudaFuncSetAttribute(k_edge_tab, cudaFuncAttributeMaxDynamicSharedMemorySize, ETAB_SMEM);
    cudaFuncSetAttribute(k_n1e, cudaFuncAttributeMaxDynamicSharedMemorySize, N1_SMEM);
    cudaFuncSetAttribute(k_n2x, cudaFuncAttributeMaxDynamicSharedMemorySize, N2_SMEM);

    float *ph, *phx, *pagg, *ptab;
    cudaGetSymbolAddress((void**)&ph,   g_h);
    cudaGetSymbolAddress((void**)&phx,  g_hx);
    cudaGetSymbolAddress((void**)&pagg, g_agg);
    cudaGetSymbolAddress((void**)&ptab, g_wtab);

    float* out = (float*)d_out;

    k_prep<<<NMOL, 128>>>(src, dst, E);
    k_build<<<LINT * (TAB_N / 128) * 2, 512, BLD_SMEM>>>(mlp_w1, mlp_b1, mlp_w2, mlp_b2);
    k_n1e<<<128, 512, N1_SMEM>>>(z, emb, cf1_w, ph, phx);

    for (int l = 0; l < LINT; l++) {
        k_edge_tab<<<NMOL * 2, 256, ETAB_SMEM>>>(pos, ptab + (long)l * (TAB_N + 1) * HDIM);
        const float* cf1n = (l + 1 < LINT) ? (cf1_w + (long)(l + 1) * HDIM * HDIM) : nullptr;
        k_n2x<<<128, 512, N2_SMEM>>>(
            pagg, cf2_w + (long)l*HDIM*HDIM, cf2_b + (long)l*HDIM,
            lin_w + (long)l*HDIM*HDIM, lin_b + (long)l*HDIM, ph,
            cf1n, phx,
            out1_w, out1_b, out2_w, out2_b, out);
    }
}

// round 16
// speedup vs baseline: 1.0380x; 1.0380x over previous
#include <cuda_runtime.h>
#include <cuda_bf16.h>
#include <math.h>
#include <stdint.h>

#define NATOMS 16384
#define NMOL   512
#define APM    32
#define HDIM   128
#define GDIM   50
#define LINT   3
#define CUTOFF 6.0f
#define TAB_N  2048
#define TILES  8
#define TS     64

// Scratch (allocation-free)
__device__ float g_h  [NATOMS * HDIM];
__device__ float g_hx [NATOMS * HDIM];
__device__ float g_agg[NATOMS * HDIM];
__device__ int   g_ucnt[NMOL];
__device__ unsigned g_upak[NMOL * 512];
__device__ int   g_ioff[NMOL * TILES * 33];
__device__ int   g_joff[NMOL * TILES * 33];
__device__ int   g_jperm[NMOL * 512];
__device__ float g_wtab[LINT * (TAB_N + 1) * HDIM];

__device__ __forceinline__ float sspf(float x) {
    const float LN2 = 0.6931471805599453f;
    if (x > 20.f) return x - LN2;
    return __logf(1.f + __expf(x)) - LN2;
}
__device__ __forceinline__ void split2(float v0, float v1, uint32_t& hi, uint32_t& lo) {
    __nv_bfloat16 h0 = __float2bfloat16(v0), h1 = __float2bfloat16(v1);
    __nv_bfloat16 l0 = __float2bfloat16(v0 - __bfloat162float(h0));
    __nv_bfloat16 l1 = __float2bfloat16(v1 - __bfloat162float(h1));
    hi = (uint32_t)__bfloat16_as_ushort(h0) | ((uint32_t)__bfloat16_as_ushort(h1) << 16);
    lo = (uint32_t)__bfloat16_as_ushort(l0) | ((uint32_t)__bfloat16_as_ushort(l1) << 16);
}
__device__ __forceinline__ void mma16816(float* d,
    uint32_t a0, uint32_t a1, uint32_t a2, uint32_t a3, uint32_t b0, uint32_t b1) {
    asm volatile(
        "mma.sync.aligned.m16n8k16.row.col.f32.bf16.bf16.f32 "
        "{%0,%1,%2,%3}, {%4,%5,%6,%7}, {%8,%9}, {%0,%1,%2,%3};"
        : "+f"(d[0]), "+f"(d[1]), "+f"(d[2]), "+f"(d[3])
        : "r"(a0), "r"(a1), "r"(a2), "r"(a3), "r"(b0), "r"(b1));
}
__device__ __forceinline__ void eaf(float d, float gofs, float step, float coeff,
                                    uint32_t& hi, uint32_t& lo) {
    float u0 = d - gofs, u1 = d - gofs - step;
    float e0 = __expf(coeff * u0 * u0);
    float e1 = __expf(coeff * u1 * u1);
    split2(e0, e1, hi, lo);
}

// ---------------------------------------------------------------------------
// Prepass with fused moff (unchanged from R13)
// ---------------------------------------------------------------------------
__global__ __launch_bounds__(128) void k_prep(const int* __restrict__ src,
                                              const int* __restrict__ dst, int E) {
    __shared__ unsigned spak[TS];
    __shared__ int scnt2[33];
    __shared__ int snu;
    __shared__ int sbounds[2];
    int m = blockIdx.x;
    int tid = threadIdx.x, lane = tid & 31, wid = tid >> 5;

    if (tid < 2) {
        int target = (m + tid) * APM;
        int lo = 0, hi = E;
        while (lo < hi) { int mid = (lo + hi) >> 1; if (src[mid] < target) lo = mid + 1; else hi = mid; }
        sbounds[tid] = lo;
    }
    __syncthreads();
    int e0 = sbounds[0], e1 = sbounds[1];

    if (wid == 0) {
        int cnt = 0;
        for (int base = e0; base < e1; base += 32) {
            int e = base + lane;
            bool p = false; unsigned pk = 0;
            if (e < e1) {
                int s = src[e] - m * APM, d2 = dst[e] - m * APM;
                if (d2 > s) { p = true; pk = (unsigned)((s << 8) | d2); }
            }
            unsigned msk = __ballot_sync(0xffffffffu, p);
            if (p) g_upak[m * 512 + cnt + __popc(msk & ((1u << lane) - 1))] = pk;
            cnt += __popc(msk);
        }
        if (lane == 0) { g_ucnt[m] = cnt; snu = cnt; }
    }
    __syncthreads();
    int nu = snu;
    int nt = (nu + TS - 1) / TS;

    for (int t = 0; t < nt; t++) {
        int nr = nu - t * TS; if (nr > TS) nr = TS;
        if (tid < TS) spak[tid] = (tid < nr) ? g_upak[m * 512 + t * TS + tid] : 0xffffffffu;
        __syncthreads();
        if (wid == 0) {
            int a = lane, c = 0;
            for (int r = 0; r < nr; r++) c += ((int)(spak[r] >> 8) < a) ? 1 : 0;
            g_ioff[(m * TILES + t) * 33 + a] = c;
            if (lane == 0) g_ioff[(m * TILES + t) * 33 + 32] = nr;
        }
        if (wid == 1) {
            int a = lane, c = 0;
            for (int r = 0; r < nr; r++) c += ((int)(spak[r] & 255) == a) ? 1 : 0;
            int x = c;
            #pragma unroll
            for (int o = 1; o < 32; o <<= 1) {
                int y = __shfl_up_sync(0xffffffffu, x, o);
                if (lane >= o) x += y;
            }
            int excl = x - c;
            g_joff[(m * TILES + t) * 33 + a] = excl;
            scnt2[a] = excl;
            if (lane == 31) g_joff[(m * TILES + t) * 33 + 32] = excl + c;
        }
        __syncthreads();
        if (tid == 0) {
            for (int r = 0; r < nr; r++) {
                int j = (int)(spak[r] & 255);
                g_jperm[m * 512 + t * TS + scnt2[j]] = r;
                scnt2[j]++;
            }
        }
        __syncthreads();
    }
}

// ---------------------------------------------------------------------------
// Fused embed + node GEMM (unchanged from R13)
// ---------------------------------------------------------------------------
#define N1_SMEM (128 * 132 * 4)

__global__ __launch_bounds__(512, 1) void k_n1e(
    const int* __restrict__ z, const float* __restrict__ emb,
    const float* __restrict__ W, float* __restrict__ h, float* __restrict__ hx)
{
    extern __shared__ uint32_t smu[];
    uint32_t* Bu = smu;
    const int tid = threadIdx.x, wid = tid >> 5, lane = tid & 31;
    const int half = wid >> 3, w8 = wid & 7;
    const int qr = lane >> 2, qc = lane & 3;

    for (int i = tid; i < 128 * 64; i += 512) {
        int kp = i >> 7, n = i & 127;
        uint32_t hh, ll;
        split2(W[(2 * kp) * 128 + n], W[(2 * kp + 1) * 128 + n], hh, ll);
        Bu[n * 132 + kp] = hh;
        Bu[n * 132 + 64 + kp] = ll;
    }
    __syncthreads();

    const int r0 = w8 * 16 + qr;
    const long base = (long)blockIdx.x * 128;
    const long za = (long)z[base + r0], zb = (long)z[base + r0 + 8];

    float acc[8][4];
    #pragma unroll
    for (int nb = 0; nb < 8; nb++) { acc[nb][0]=0.f; acc[nb][1]=0.f; acc[nb][2]=0.f; acc[nb][3]=0.f; }

    #pragma unroll
    for (int ks = 0; ks < 8; ks++) {
        const float* xr0 = emb + za * 128 + ks * 16 + 2 * qc;
        const float* xr1 = emb + zb * 128 + ks * 16 + 2 * qc;
        float2 v00 = *(const float2*)xr0;
        float2 v01 = *(const float2*)(xr0 + 8);
        float2 v10 = *(const float2*)xr1;
        float2 v11 = *(const float2*)(xr1 + 8);
        if (half == 0) {
            *(float2*)(h + (base + r0) * 128 + ks * 16 + 2 * qc)         = v00;
            *(float2*)(h + (base + r0) * 128 + ks * 16 + 8 + 2 * qc)     = v01;
            *(float2*)(h + (base + r0 + 8) * 128 + ks * 16 + 2 * qc)     = v10;
            *(float2*)(h + (base + r0 + 8) * 128 + ks * 16 + 8 + 2 * qc) = v11;
        }
        uint32_t aH0,aH1,aH2,aH3,aL0,aL1,aL2,aL3;
        split2(v00.x, v00.y, aH0, aL0);
        split2(v10.x, v10.y, aH1, aL1);
        split2(v01.x, v01.y, aH2, aL2);
        split2(v11.x, v11.y, aH3, aL3);
        #pragma unroll
        for (int nb = 0; nb < 8; nb++) {
            int noff = ((half * 8 + nb) * 8 + qr) * 132 + ks * 8 + qc;
            uint32_t bh0 = Bu[noff], bh1 = Bu[noff + 4];
            mma16816(acc[nb], aH0, aH1, aH2, aH3, bh0, bh1);
            mma16816(acc[nb], aL0, aL1, aL2, aL3, bh0, bh1);
            uint32_t bl0 = Bu[noff + 64], bl1 = Bu[noff + 68];
            mma16816(acc[nb], aH0, aH1, aH2, aH3, bl0, bl1);
        }
    }

    #pragma unroll
    for (int nb = 0; nb < 8; nb++) {
        int c = (half * 8 + nb) * 8 + 2 * qc;
        *(float2*)(hx + (base + r0) * 128 + c)     = make_float2(acc[nb][0], acc[nb][1]);
        *(float2*)(hx + (base + r0 + 8) * 128 + c) = make_float2(acc[nb][2], acc[nb][3]);
    }
}

// ---------------------------------------------------------------------------
// Fused node chain + output head (unchanged from R13)
// ---------------------------------------------------------------------------
#define N2_OB1 0
#define N2_OB2 16896
#define N2_OT1 33792
#define N2_OS2 50688
#define N2_OSL 50816
#define N2_OSA 50944
#define N2_SMEM ((51072) * 4)

__global__ __launch_bounds__(512, 1) void k_n2x(
    const float* __restrict__ agg,
    const float* __restrict__ W2, const float* __restrict__ b2,
    const float* __restrict__ Wl, const float* __restrict__ lb,
    float* __restrict__ h,
    const float* __restrict__ cf1n, float* __restrict__ hx,
    const float* __restrict__ o1w, const float* __restrict__ o1b,
    const float* __restrict__ o2w, const float* __restrict__ o2b,
    float* __restrict__ out)
{
    extern __shared__ uint32_t smu[];
    uint32_t* Bu1 = smu + N2_OB1;
    uint32_t* Bu2 = smu + N2_OB2;
    uint32_t* T1  = smu + N2_OT1;
    float* sb2 = (float*)(smu + N2_OS2);
    float* slb = (float*)(smu + N2_OSL);
    float* satom = (float*)(smu + N2_OSA);

    const int tid = threadIdx.x, wid = tid >> 5, lane = tid & 31;
    const int half = wid >> 3, w8 = wid & 7;
    const int qr = lane >> 2, qc = lane & 3;

    for (int i = tid; i < 128 * 64; i += 512) {
        int kp = i >> 7, n = i & 127;
        uint32_t hh, ll;
        split2(W2[(2 * kp) * 128 + n], W2[(2 * kp + 1) * 128 + n], hh, ll);
        Bu1[n * 132 + kp] = hh; Bu1[n * 132 + 64 + kp] = ll;
        split2(Wl[(2 * kp) * 128 + n], Wl[(2 * kp + 1) * 128 + n], hh, ll);
        Bu2[n * 132 + kp] = hh; Bu2[n * 132 + 64 + kp] = ll;
    }
    if (tid < 128) { sb2[tid] = b2[tid]; slb[tid] = lb[tid]; }
    __syncthreads();

    const int r0 = w8 * 16 + qr;
    const long base = (long)blockIdx.x * 128;

    // GEMM1: agg @ W2 -> ssp -> T1
    {
        float acc[8][4];
        #pragma unroll
        for (int nb = 0; nb < 8; nb++) { acc[nb][0]=0.f; acc[nb][1]=0.f; acc[nb][2]=0.f; acc[nb][3]=0.f; }
        #pragma unroll
        for (int ks = 0; ks < 8; ks++) {
            const float* xr = agg + (base + r0) * 128 + ks * 16 + 2 * qc;
            float2 v00 = *(const float2*)xr;
            float2 v01 = *(const float2*)(xr + 8);
            float2 v10 = *(const float2*)(xr + 8 * 128);
            float2 v11 = *(const float2*)(xr + 8 * 128 + 8);
            uint32_t aH0,aH1,aH2,aH3,aL0,aL1,aL2,aL3;
            split2(v00.x, v00.y, aH0, aL0);
            split2(v10.x, v10.y, aH1, aL1);
            split2(v01.x, v01.y, aH2, aL2);
            split2(v11.x, v11.y, aH3, aL3);
            #pragma unroll
            for (int nb = 0; nb < 8; nb++) {
                int noff = ((half * 8 + nb) * 8 + qr) * 132 + ks * 8 + qc;
                uint32_t bh0 = Bu1[noff], bh1 = Bu1[noff + 4];
                mma16816(acc[nb], aH0, aH1, aH2, aH3, bh0, bh1);
                mma16816(acc[nb], aL0, aL1, aL2, aL3, bh0, bh1);
                uint32_t bl0 = Bu1[noff + 64], bl1 = Bu1[noff + 68];
                mma16816(acc[nb], aH0, aH1, aH2, aH3, bl0, bl1);
            }
        }
        #pragma unroll
        for (int nb = 0; nb < 8; nb++) {
            int c = (half * 8 + nb) * 8 + 2 * qc;
            int kp = (c >> 1);
            float bx = sb2[c], by = sb2[c + 1];
            uint32_t hh, ll;
            split2(sspf(acc[nb][0] + bx), sspf(acc[nb][1] + by), hh, ll);
            T1[r0 * 132 + kp] = hh; T1[r0 * 132 + 64 + kp] = ll;
            split2(sspf(acc[nb][2] + bx), sspf(acc[nb][3] + by), hh, ll);
            T1[(r0 + 8) * 132 + kp] = hh; T1[(r0 + 8) * 132 + 64 + kp] = ll;
        }
    }
    __syncthreads();

    if (cf1n) {
        for (int i = tid; i < 128 * 64; i += 512) {
            int kp = i >> 7, n = i & 127;
            uint32_t hh, ll;
            split2(cf1n[(2 * kp) * 128 + n], cf1n[(2 * kp + 1) * 128 + n], hh, ll);
            Bu1[n * 132 + kp] = hh; Bu1[n * 132 + 64 + kp] = ll;
        }
    }

    // GEMM2: T1 @ Wl, residual -> h; re-split h_new into T1 (always)
    {
        float acc[8][4];
        #pragma unroll
        for (int nb = 0; nb < 8; nb++) { acc[nb][0]=0.f; acc[nb][1]=0.f; acc[nb][2]=0.f; acc[nb][3]=0.f; }
        #pragma unroll
        for (int ks = 0; ks < 8; ks++) {
            int xo0 = r0 * 132 + ks * 8 + qc;
            int xo1 = (r0 + 8) * 132 + ks * 8 + qc;
            uint32_t aH0 = T1[xo0],      aH1 = T1[xo1];
            uint32_t aH2 = T1[xo0 + 4],  aH3 = T1[xo1 + 4];
            uint32_t aL0 = T1[xo0 + 64], aL1 = T1[xo1 + 64];
            uint32_t aL2 = T1[xo0 + 68], aL3 = T1[xo1 + 68];
            #pragma unroll
            for (int nb = 0; nb < 8; nb++) {
                int noff = ((half * 8 + nb) * 8 + qr) * 132 + ks * 8 + qc;
                uint32_t bh0 = Bu2[noff], bh1 = Bu2[noff + 4];
                mma16816(acc[nb], aH0, aH1, aH2, aH3, bh0, bh1);
                mma16816(acc[nb], aL0, aL1, aL2, aL3, bh0, bh1);
                uint32_t bl0 = Bu2[noff + 64], bl1 = Bu2[noff + 68];
                mma16816(acc[nb], aH0, aH1, aH2, aH3, bl0, bl1);
            }
        }
        #pragma unroll
        for (int nb = 0; nb < 8; nb++) {
            int c = (half * 8 + nb) * 8 + 2 * qc;
            float bx = slb[c], by = slb[c + 1];
            float* y0 = h + (base + r0) * 128 + c;
            float* y1 = h + (base + r0 + 8) * 128 + c;
            float2 p0 = *(float2*)y0, p1 = *(float2*)y1;
            float v0 = p0.x + acc[nb][0] + bx, v1 = p0.y + acc[nb][1] + by;
            float v2 = p1.x + acc[nb][2] + bx, v3 = p1.y + acc[nb][3] + by;
            *(float2*)y0 = make_float2(v0, v1);
            *(float2*)y1 = make_float2(v2, v3);
            int kp = c >> 1;
            uint32_t hh, ll;
            split2(v0, v1, hh, ll);
            T1[r0 * 132 + kp] = hh; T1[r0 * 132 + 64 + kp] = ll;
            split2(v2, v3, hh, ll);
            T1[(r0 + 8) * 132 + kp] = hh; T1[(r0 + 8) * 132 + 64 + kp] = ll;
        }
    }
    __syncthreads();   // T1 (h_new split) complete for all rows

    if (cf1n) {
        // GEMM3: hx = h_new @ cf1n
        float acc[8][4];
        #pragma unroll
        for (int nb = 0; nb < 8; nb++) { acc[nb][0]=0.f; acc[nb][1]=0.f; acc[nb][2]=0.f; acc[nb][3]=0.f; }
        #pragma unroll
        for (int ks = 0; ks < 8; ks++) {
            int xo0 = r0 * 132 + ks * 8 + qc;
            int xo1 = (r0 + 8) * 132 + ks * 8 + qc;
            uint32_t aH0 = T1[xo0],      aH1 = T1[xo1];
            uint32_t aH2 = T1[xo0 + 4],  aH3 = T1[xo1 + 4];
            uint32_t aL0 = T1[xo0 + 64], aL1 = T1[xo1 + 64];
            uint32_t aL2 = T1[xo0 + 68], aL3 = T1[xo1 + 68];
            #pragma unroll
            for (int nb = 0; nb < 8; nb++) {
                int noff = ((half * 8 + nb) * 8 + qr) * 132 + ks * 8 + qc;
                uint32_t bh0 = Bu1[noff], bh1 = Bu1[noff + 4];
                mma16816(acc[nb], aH0, aH1, aH2, aH3, bh0, bh1);
                mma16816(acc[nb], aL0, aL1, aL2, aL3, bh0, bh1);
                uint32_t bl0 = Bu1[noff + 64], bl1 = Bu1[noff + 68];
                mma16816(acc[nb], aH0, aH1, aH2, aH3, bl0, bl1);
            }
        }
        #pragma unroll
        for (int nb = 0; nb < 8; nb++) {
            int c = (half * 8 + nb) * 8 + 2 * qc;
            *(float2*)(hx + (base + r0) * 128 + c)     = make_float2(acc[nb][0], acc[nb][1]);
            *(float2*)(hx + (base + r0 + 8) * 128 + c) = make_float2(acc[nb][2], acc[nb][3]);
        }
        return;
    }

    // ---- Fused output head (last layer) ----
    for (int i = tid; i < 64 * 64; i += 512) {
        int kp = i >> 6, n = i & 63;
        uint32_t hh, ll;
        split2(o1w[(2 * kp) * 64 + n], o1w[(2 * kp + 1) * 64 + n], hh, ll);
        Bu1[n * 132 + kp] = hh; Bu1[n * 132 + 64 + kp] = ll;
    }
    if (tid < 64) { sb2[tid] = o1b[tid]; slb[tid] = o2w[tid]; }
    if (tid < 128) satom[tid] = 0.f;
    __syncthreads();

    {
        float acc[4][4];
        #pragma unroll
        for (int nb = 0; nb < 4; nb++) { acc[nb][0]=0.f; acc[nb][1]=0.f; acc[nb][2]=0.f; acc[nb][3]=0.f; }
        #pragma unroll
        for (int ks = 0; ks < 8; ks++) {
            int xo0 = r0 * 132 + ks * 8 + qc;
            int xo1 = (r0 + 8) * 132 + ks * 8 + qc;
            uint32_t aH0 = T1[xo0],      aH1 = T1[xo1];
            uint32_t aH2 = T1[xo0 + 4],  aH3 = T1[xo1 + 4];
            uint32_t aL0 = T1[xo0 + 64], aL1 = T1[xo1 + 64];
            uint32_t aL2 = T1[xo0 + 68], aL3 = T1[xo1 + 68];
            #pragma unroll
            for (int nb = 0; nb < 4; nb++) {
                int cb2 = half * 4 + nb;
                int noff = (cb2 * 8 + qr) * 132 + ks * 8 + qc;
                uint32_t bh0 = Bu1[noff], bh1 = Bu1[noff + 4];
                mma16816(acc[nb], aH0, aH1, aH2, aH3, bh0, bh1);
                mma16816(acc[nb], aL0, aL1, aL2, aL3, bh0, bh1);
                uint32_t bl0 = Bu1[noff + 64], bl1 = Bu1[noff + 68];
                mma16816(acc[nb], aH0, aH1, aH2, aH3, bl0, bl1);
            }
        }
        float P0 = 0.f, P1 = 0.f;
        #pragma unroll
        for (int nb = 0; nb < 4; nb++) {
            int c = (half * 4 + nb) * 8 + 2 * qc;
            float bx = sb2[c], by = sb2[c + 1];
            float wx = slb[c], wy = slb[c + 1];
            P0 += sspf(acc[nb][0] + bx) * wx + sspf(acc[nb][1] + by) * wy;
            P1 += sspf(acc[nb][2] + bx) * wx + sspf(acc[nb][3] + by) * wy;
        }
        atomicAdd(&satom[r0], P0);
        atomicAdd(&satom[r0 + 8], P1);
    }
    __syncthreads();

    if (tid < 4) {
        float s = 0.f;
        #pragma unroll
        for (int a = 0; a < 32; a++) s += satom[tid * 32 + a];
        out[blockIdx.x * 4 + tid] = s + 32.f * o2b[0];
    }
}

// ---------------------------------------------------------------------------
// Table builder, N-split (unchanged from R13)
// ---------------------------------------------------------------------------
#define BLD_SMEM (34304 * 4)

__global__ __launch_bounds__(512, 1)
void k_build(const float* __restrict__ w1all, const float* __restrict__ b1all,
             const float* __restrict__ w2all, const float* __restrict__ b2all)
{
    extern __shared__ uint32_t smu[];
    uint32_t* B1u = smu;
    uint32_t* B2u = smu + 8704;
    uint32_t* T1  = smu + 17152;
    float* sb1 = (float*)(smu + 34048);
    float* sb2 = (float*)(smu + 34176);

    const int tpl = TAB_N / 128;
    const int ch = blockIdx.x & 1;
    const int t  = (blockIdx.x >> 1) % tpl;
    const int l  = (blockIdx.x >> 1) / tpl;
    const float* w1 = w1all + (long)l * GDIM * HDIM;
    const float* b1 = b1all + (long)l * HDIM;
    const float* w2 = w2all + (long)l * HDIM * HDIM;
    const float* b2 = b2all + (long)l * HDIM;

    const int tid = threadIdx.x, wid = tid >> 5, lane = tid & 31;
    const int half = wid >> 3, w8 = wid & 7;
    const int qr = lane >> 2, qc = lane & 3;

    for (int i = tid; i < 128 * 32; i += 512) {
        int kp = i >> 7, n = i & 127, k = 2 * kp;
        float v0 = (k < GDIM)     ? w1[k * 128 + n]       : 0.f;
        float v1 = (k + 1 < GDIM) ? w1[(k + 1) * 128 + n] : 0.f;
        uint32_t h, lv; split2(v0, v1, h, lv);
        B1u[n * 68 + kp] = h;
        B1u[n * 68 + 32 + kp] = lv;
    }
    for (int i = tid; i < 64 * 64; i += 512) {
        int kp = i >> 6, nl = i & 63;
        int n = ch * 64 + nl;
        uint32_t h, lv;
        split2(w2[(2 * kp) * 128 + n], w2[(2 * kp + 1) * 128 + n], h, lv);
        B2u[nl * 132 + kp] = h;
        B2u[nl * 132 + 64 + kp] = lv;
    }
    if (tid < 128) { sb1[tid] = b1[tid]; sb2[tid] = b2[tid]; }
    __syncthreads();

    const float step  = CUTOFF / (GDIM - 1);
    const float coeff = -0.5f / (step * step);
    const float PIOC  = 3.14159265358979f / CUTOFF;
    const float DELTA = CUTOFF / (float)TAB_N;
    const int r0 = w8 * 16 + qr;

    float dv0 = (float)(t * 128 + r0) * DELTA;
    float dv1 = (float)(t * 128 + r0 + 8) * DELTA;

    uint32_t aH[4][4], aL[4][4];
    #pragma unroll
    for (int ks = 0; ks < 4; ks++) {
        float g0 = (float)(ks * 16 + 2 * qc) * step;
        eaf(dv0, g0,            step, coeff, aH[ks][0], aL[ks][0]);
        eaf(dv1, g0,            step, coeff, aH[ks][1], aL[ks][1]);
        eaf(dv0, g0 + 8.f*step, step, coeff, aH[ks][2], aL[ks][2]);
        eaf(dv1, g0 + 8.f*step, step, coeff, aH[ks][3], aL[ks][3]);
    }

    #pragma unroll
    for (int nb = 0; nb < 8; nb++) {
        float acc[4] = {0.f, 0.f, 0.f, 0.f};
        #pragma unroll
        for (int ks = 0; ks < 4; ks++) {
            int noff = ((half * 8 + nb) * 8 + qr) * 68 + ks * 8 + qc;
            uint32_t bh0 = B1u[noff], bh1 = B1u[noff + 4];
            mma16816(acc, aH[ks][0], aH[ks][1], aH[ks][2], aH[ks][3], bh0, bh1);
            mma16816(acc, aL[ks][0], aL[ks][1], aL[ks][2], aL[ks][3], bh0, bh1);
            uint32_t bl0 = B1u[noff + 32], bl1 = B1u[noff + 36];
            mma16816(acc, aH[ks][0], aH[ks][1], aH[ks][2], aH[ks][3], bl0, bl1);
        }
        int c = (half * 8 + nb) * 8 + 2 * qc;
        int kp = c >> 1;
        float bx = sb1[c], by = sb1[c + 1];
        uint32_t hh, ll;
        split2(sspf(acc[0] + bx), sspf(acc[1] + by), hh, ll);
        T1[r0 * 132 + kp] = hh; T1[r0 * 132 + 64 + kp] = ll;
        split2(sspf(acc[2] + bx), sspf(acc[3] + by), hh, ll);
        T1[(r0 + 8) * 132 + kp] = hh; T1[(r0 + 8) * 132 + 64 + kp] = ll;
    }
    __syncthreads();

    float acc2[4][4];
    #pragma unroll
    for (int nb = 0; nb < 4; nb++) { acc2[nb][0]=0.f; acc2[nb][1]=0.f; acc2[nb][2]=0.f; acc2[nb][3]=0.f; }
    #pragma unroll
    for (int ks = 0; ks < 8; ks++) {
        int xo0 = r0 * 132 + ks * 8 + qc;
        int xo1 = (r0 + 8) * 132 + ks * 8 + qc;
        uint32_t aH0 = T1[xo0],      aH1 = T1[xo1];
        uint32_t aH2 = T1[xo0 + 4],  aH3 = T1[xo1 + 4];
        uint32_t aL0 = T1[xo0 + 64], aL1 = T1[xo1 + 64];
        uint32_t aL2 = T1[xo0 + 68], aL3 = T1[xo1 + 68];
        #pragma unroll
        for (int nb = 0; nb < 4; nb++) {
            int cb2 = half * 4 + nb;
            int noff = (cb2 * 8 + qr) * 132 + ks * 8 + qc;
            uint32_t bh0 = B2u[noff], bh1 = B2u[noff + 4];
            mma16816(acc2[nb], aH0, aH1, aH2, aH3, bh0, bh1);
            mma16816(acc2[nb], aL0, aL1, aL2, aL3, bh0, bh1);
            uint32_t bl0 = B2u[noff + 64], bl1 = B2u[noff + 68];
            mma16816(acc2[nb], aH0, aH1, aH2, aH3, bl0, bl1);
        }
    }

    float cc0 = 0.5f * (cosf(dv0 * PIOC) + 1.f);
    float cc1 = 0.5f * (cosf(dv1 * PIOC) + 1.f);
    float* trow = g_wtab + ((long)l * (TAB_N + 1) + t * 128 + r0) * 128;
    #pragma unroll
    for (int nb = 0; nb < 4; nb++) {
        int c = ch * 64 + (half * 4 + nb) * 8 + 2 * qc;
        float bx = sb2[c], by = sb2[c + 1];
        *(float2*)(trow + c) =
            make_float2((acc2[nb][0] + bx) * cc0, (acc2[nb][1] + by) * cc0);
        *(float2*)(trow + 8 * 128 + c) =
            make_float2((acc2[nb][2] + bx) * cc1, (acc2[nb][3] + by) * cc1);
    }
    if (t == 0 && ch == 0 && tid < 128)
        g_wtab[((long)l * (TAB_N + 1) + TAB_N) * 128 + tid] = 0.f;
}

// ---------------------------------------------------------------------------
// Edge-centric table-lookup kernel: CTA = (molecule, 64-col half), 8 warps.
// One warp per edge (strided); inline lerp; both directions via SMEM atomics.
// No syncs in the main loop. ~18 KB static SMEM.
// ---------------------------------------------------------------------------
__global__ __launch_bounds__(256)
void k_edge_tab(const float* __restrict__ pos, const float* __restrict__ wtab)
{
    __shared__ float hxs [APM * 68];
    __shared__ float sagg[APM * 68];
    __shared__ float ps[96];

    const int tid = threadIdx.x, wid = tid >> 5, lane = tid & 31;
    const int m = blockIdx.x >> 1, ch = blockIdx.x & 1;
    const int cb = ch * 64;
    const float SCALE = (float)TAB_N / CUTOFF;

    const int nu = g_ucnt[m];

    for (int i = tid; i < APM * 64; i += 256) {
        int a = i >> 6, c = i & 63;
        hxs[a * 68 + c] = g_hx[(long)(m * APM + a) * 128 + cb + c];
        sagg[a * 68 + c] = 0.f;
    }
    if (tid < 96) ps[tid] = pos[m * 96 + tid];
    __syncthreads();

    const int c2 = lane * 2;
    const float* tabc = wtab + cb + c2;

    for (int e = wid; e < nu; e += 8) {
        unsigned pk = g_upak[m * 512 + e];        // broadcast load
        int il = (int)(pk >> 8), jl = (int)(pk & 255);
        float dx = ps[3*il]   - ps[3*jl];
        float dy = ps[3*il+1] - ps[3*jl+1];
        float dz = ps[3*il+2] - ps[3*jl+2];
        float d = sqrtf(dx*dx + dy*dy + dz*dz);
        float tt = d * SCALE;
        int i0 = (int)tt;
        i0 = (i0 > TAB_N - 1) ? (TAB_N - 1) : i0;
        float f = tt - (float)i0;
        const float* T = tabc + (long)i0 * 128;
        float2 wa = *(const float2*)T;
        float2 wb = *(const float2*)(T + 128);
        float w0 = wa.x + f * (wb.x - wa.x);
        float w1 = wa.y + f * (wb.y - wa.y);
        float2 hj = *(const float2*)&hxs[jl * 68 + c2];
        float2 hi_ = *(const float2*)&hxs[il * 68 + c2];
        atomicAdd(&sagg[il * 68 + c2],     w0 * hj.x);
        atomicAdd(&sagg[il * 68 + c2 + 1], w1 * hj.y);
        atomicAdd(&sagg[jl * 68 + c2],     w0 * hi_.x);
        atomicAdd(&sagg[jl * 68 + c2 + 1], w1 * hi_.y);
    }
    __syncthreads();

    for (int i = tid; i < APM * 64; i += 256) {
        int a = i >> 6, c = i & 63;
        g_agg[(long)(m * APM + a) * 128 + cb + c] = sagg[a * 68 + c];
    }
}

// ---------------------------------------------------------------------------
extern "C" void kernel_launch(void* const* d_in, const int* in_sizes, int n_in,
                              void* d_out, int out_size)
{
    const int*   z       = (const int*)  d_in[0];
    const float* pos     = (const float*)d_in[1];
    const int*   ei      = (const int*)  d_in[3];
    const float* emb     = (const float*)d_in[4];
    const float* mlp_w1  = (const float*)d_in[5];
    const float* mlp_b1  = (const float*)d_in[6];
    const float* mlp_w2  = (const float*)d_in[7];
    const float* mlp_b2  = (const float*)d_in[8];
    const float* cf1_w   = (const float*)d_in[9];
    const float* cf2_w   = (const float*)d_in[10];
    const float* cf2_b   = (const float*)d_in[11];
    const float* lin_w   = (const float*)d_in[12];
    const float* lin_b   = (const float*)d_in[13];
    const float* out1_w  = (const float*)d_in[14];
    const float* out1_b  = (const float*)d_in[15];
    const float* out2_w  = (const float*)d_in[16];
    const float* out2_b  = (const float*)d_in[17];

    int E = in_sizes[3] / 2;
    const int* src = ei;
    const int* dst = ei + E;

    cudaFuncSetAttribute(k_build, cudaFuncAttributeMaxDynamicSharedMemorySize, BLD_SMEM);
    cudaFuncSetAttribute(k_n1e, cudaFuncAttributeMaxDynamicSharedMemorySize, N1_SMEM);
    cudaFuncSetAttribute(k_n2x, cudaFuncAttributeMaxDynamicSharedMemorySize, N2_SMEM);

    float *ph, *phx, *pagg, *ptab;
    cudaGetSymbolAddress((void**)&ph,   g_h);
    cudaGetSymbolAddress((void**)&phx,  g_hx);
    cudaGetSymbolAddress((void**)&pagg, g_agg);
    cudaGetSymbolAddress((void**)&ptab, g_wtab);

    float* out = (float*)d_out;

    k_prep<<<NMOL, 128>>>(src, dst, E);
    k_build<<<LINT * (TAB_N / 128) * 2, 512, BLD_SMEM>>>(mlp_w1, mlp_b1, mlp_w2, mlp_b2);
    k_n1e<<<128, 512, N1_SMEM>>>(z, emb, cf1_w, ph, phx);

    for (int l = 0; l < LINT; l++) {
        k_edge_tab<<<NMOL * 2, 256>>>(pos, ptab + (long)l * (TAB_N + 1) * HDIM);
        const float* cf1n = (l + 1 < LINT) ? (cf1_w + (long)(l + 1) * HDIM * HDIM) : nullptr;
        k_n2x<<<128, 512, N2_SMEM>>>(
            pagg, cf2_w + (long)l*HDIM*HDIM, cf2_b + (long)l*HDIM,
            lin_w + (long)l*HDIM*HDIM, lin_b + (long)l*HDIM, ph,
            cf1n, phx,
            out1_w, out1_b, out2_w, out2_b, out);
    }
}

// round 17
// speedup vs baseline: 1.1444x; 1.1025x over previous
#include <cuda_runtime.h>
#include <cuda_bf16.h>
#include <math.h>
#include <stdint.h>

#define NATOMS 16384
#define NMOL   512
#define APM    32
#define HDIM   128
#define GDIM   50
#define LINT   3
#define CUTOFF 6.0f
#define TAB_N  2048
#define TILES  8
#define TS     64

// Scratch (allocation-free)
__device__ float g_h  [NATOMS * HDIM];
__device__ float g_hx [NATOMS * HDIM];
__device__ float g_agg[NATOMS * HDIM];
__device__ int   g_ucnt[NMOL];
__device__ unsigned g_upak[NMOL * 512];
__device__ int   g_ioff[NMOL * TILES * 33];
__device__ int   g_joff[NMOL * TILES * 33];
__device__ int   g_jperm[NMOL * 512];
__device__ float g_wtab[LINT * (TAB_N + 1) * HDIM];

__device__ __forceinline__ float sspf(float x) {
    const float LN2 = 0.6931471805599453f;
    if (x > 20.f) return x - LN2;
    return __logf(1.f + __expf(x)) - LN2;
}
__device__ __forceinline__ void split2(float v0, float v1, uint32_t& hi, uint32_t& lo) {
    __nv_bfloat16 h0 = __float2bfloat16(v0), h1 = __float2bfloat16(v1);
    __nv_bfloat16 l0 = __float2bfloat16(v0 - __bfloat162float(h0));
    __nv_bfloat16 l1 = __float2bfloat16(v1 - __bfloat162float(h1));
    hi = (uint32_t)__bfloat16_as_ushort(h0) | ((uint32_t)__bfloat16_as_ushort(h1) << 16);
    lo = (uint32_t)__bfloat16_as_ushort(l0) | ((uint32_t)__bfloat16_as_ushort(l1) << 16);
}
__device__ __forceinline__ void mma16816(float* d,
    uint32_t a0, uint32_t a1, uint32_t a2, uint32_t a3, uint32_t b0, uint32_t b1) {
    asm volatile(
        "mma.sync.aligned.m16n8k16.row.col.f32.bf16.bf16.f32 "
        "{%0,%1,%2,%3}, {%4,%5,%6,%7}, {%8,%9}, {%0,%1,%2,%3};"
        : "+f"(d[0]), "+f"(d[1]), "+f"(d[2]), "+f"(d[3])
        : "r"(a0), "r"(a1), "r"(a2), "r"(a3), "r"(b0), "r"(b1));
}
__device__ __forceinline__ void eaf(float d, float gofs, float step, float coeff,
                                    uint32_t& hi, uint32_t& lo) {
    float u0 = d - gofs, u1 = d - gofs - step;
    float e0 = __expf(coeff * u0 * u0);
    float e1 = __expf(coeff * u1 * u1);
    split2(e0, e1, hi, lo);
}

// ---------------------------------------------------------------------------
// Prepass with fused moff (unchanged)
// ---------------------------------------------------------------------------
__global__ __launch_bounds__(128) void k_prep(const int* __restrict__ src,
                                              const int* __restrict__ dst, int E) {
    __shared__ unsigned spak[TS];
    __shared__ int scnt2[33];
    __shared__ int snu;
    __shared__ int sbounds[2];
    int m = blockIdx.x;
    int tid = threadIdx.x, lane = tid & 31, wid = tid >> 5;

    if (tid < 2) {
        int target = (m + tid) * APM;
        int lo = 0, hi = E;
        while (lo < hi) { int mid = (lo + hi) >> 1; if (src[mid] < target) lo = mid + 1; else hi = mid; }
        sbounds[tid] = lo;
    }
    __syncthreads();
    int e0 = sbounds[0], e1 = sbounds[1];

    if (wid == 0) {
        int cnt = 0;
        for (int base = e0; base < e1; base += 32) {
            int e = base + lane;
            bool p = false; unsigned pk = 0;
            if (e < e1) {
                int s = src[e] - m * APM, d2 = dst[e] - m * APM;
                if (d2 > s) { p = true; pk = (unsigned)((s << 8) | d2); }
            }
            unsigned msk = __ballot_sync(0xffffffffu, p);
            if (p) g_upak[m * 512 + cnt + __popc(msk & ((1u << lane) - 1))] = pk;
            cnt += __popc(msk);
        }
        if (lane == 0) { g_ucnt[m] = cnt; snu = cnt; }
    }
    __syncthreads();
    int nu = snu;
    int nt = (nu + TS - 1) / TS;

    for (int t = 0; t < nt; t++) {
        int nr = nu - t * TS; if (nr > TS) nr = TS;
        if (tid < TS) spak[tid] = (tid < nr) ? g_upak[m * 512 + t * TS + tid] : 0xffffffffu;
        __syncthreads();
        if (wid == 0) {
            int a = lane, c = 0;
            for (int r = 0; r < nr; r++) c += ((int)(spak[r] >> 8) < a) ? 1 : 0;
            g_ioff[(m * TILES + t) * 33 + a] = c;
            if (lane == 0) g_ioff[(m * TILES + t) * 33 + 32] = nr;
        }
        if (wid == 1) {
            int a = lane, c = 0;
            for (int r = 0; r < nr; r++) c += ((int)(spak[r] & 255) == a) ? 1 : 0;
            int x = c;
            #pragma unroll
            for (int o = 1; o < 32; o <<= 1) {
                int y = __shfl_up_sync(0xffffffffu, x, o);
                if (lane >= o) x += y;
            }
            int excl = x - c;
            g_joff[(m * TILES + t) * 33 + a] = excl;
            scnt2[a] = excl;
            if (lane == 31) g_joff[(m * TILES + t) * 33 + 32] = excl + c;
        }
        __syncthreads();
        if (tid == 0) {
            for (int r = 0; r < nr; r++) {
                int j = (int)(spak[r] & 255);
                g_jperm[m * 512 + t * TS + scnt2[j]] = r;
                scnt2[j]++;
            }
        }
        __syncthreads();
    }
}

// ---------------------------------------------------------------------------
// Fused embed + node GEMM (unchanged)
// ---------------------------------------------------------------------------
#define N1_SMEM (128 * 132 * 4)

__global__ __launch_bounds__(512, 1) void k_n1e(
    const int* __restrict__ z, const float* __restrict__ emb,
    const float* __restrict__ W, float* __restrict__ h, float* __restrict__ hx)
{
    extern __shared__ uint32_t smu[];
    uint32_t* Bu = smu;
    const int tid = threadIdx.x, wid = tid >> 5, lane = tid & 31;
    const int half = wid >> 3, w8 = wid & 7;
    const int qr = lane >> 2, qc = lane & 3;

    for (int i = tid; i < 128 * 64; i += 512) {
        int kp = i >> 7, n = i & 127;
        uint32_t hh, ll;
        split2(W[(2 * kp) * 128 + n], W[(2 * kp + 1) * 128 + n], hh, ll);
        Bu[n * 132 + kp] = hh;
        Bu[n * 132 + 64 + kp] = ll;
    }
    __syncthreads();

    const int r0 = w8 * 16 + qr;
    const long base = (long)blockIdx.x * 128;
    const long za = (long)z[base + r0], zb = (long)z[base + r0 + 8];

    float acc[8][4];
    #pragma unroll
    for (int nb = 0; nb < 8; nb++) { acc[nb][0]=0.f; acc[nb][1]=0.f; acc[nb][2]=0.f; acc[nb][3]=0.f; }

    #pragma unroll
    for (int ks = 0; ks < 8; ks++) {
        const float* xr0 = emb + za * 128 + ks * 16 + 2 * qc;
        const float* xr1 = emb + zb * 128 + ks * 16 + 2 * qc;
        float2 v00 = *(const float2*)xr0;
        float2 v01 = *(const float2*)(xr0 + 8);
        float2 v10 = *(const float2*)xr1;
        float2 v11 = *(const float2*)(xr1 + 8);
        if (half == 0) {
            *(float2*)(h + (base + r0) * 128 + ks * 16 + 2 * qc)         = v00;
            *(float2*)(h + (base + r0) * 128 + ks * 16 + 8 + 2 * qc)     = v01;
            *(float2*)(h + (base + r0 + 8) * 128 + ks * 16 + 2 * qc)     = v10;
            *(float2*)(h + (base + r0 + 8) * 128 + ks * 16 + 8 + 2 * qc) = v11;
        }
        uint32_t aH0,aH1,aH2,aH3,aL0,aL1,aL2,aL3;
        split2(v00.x, v00.y, aH0, aL0);
        split2(v10.x, v10.y, aH1, aL1);
        split2(v01.x, v01.y, aH2, aL2);
        split2(v11.x, v11.y, aH3, aL3);
        #pragma unroll
        for (int nb = 0; nb < 8; nb++) {
            int noff = ((half * 8 + nb) * 8 + qr) * 132 + ks * 8 + qc;
            uint32_t bh0 = Bu[noff], bh1 = Bu[noff + 4];
            mma16816(acc[nb], aH0, aH1, aH2, aH3, bh0, bh1);
            mma16816(acc[nb], aL0, aL1, aL2, aL3, bh0, bh1);
            uint32_t bl0 = Bu[noff + 64], bl1 = Bu[noff + 68];
            mma16816(acc[nb], aH0, aH1, aH2, aH3, bl0, bl1);
        }
    }

    #pragma unroll
    for (int nb = 0; nb < 8; nb++) {
        int c = (half * 8 + nb) * 8 + 2 * qc;
        *(float2*)(hx + (base + r0) * 128 + c)     = make_float2(acc[nb][0], acc[nb][1]);
        *(float2*)(hx + (base + r0 + 8) * 128 + c) = make_float2(acc[nb][2], acc[nb][3]);
    }
}

// ---------------------------------------------------------------------------
// Fused node chain + output head (unchanged)
// ---------------------------------------------------------------------------
#define N2_OB1 0
#define N2_OB2 16896
#define N2_OT1 33792
#define N2_OS2 50688
#define N2_OSL 50816
#define N2_OSA 50944
#define N2_SMEM ((51072) * 4)

__global__ __launch_bounds__(512, 1) void k_n2x(
    const float* __restrict__ agg,
    const float* __restrict__ W2, const float* __restrict__ b2,
    const float* __restrict__ Wl, const float* __restrict__ lb,
    float* __restrict__ h,
    const float* __restrict__ cf1n, float* __restrict__ hx,
    const float* __restrict__ o1w, const float* __restrict__ o1b,
    const float* __restrict__ o2w, const float* __restrict__ o2b,
    float* __restrict__ out)
{
    extern __shared__ uint32_t smu[];
    uint32_t* Bu1 = smu + N2_OB1;
    uint32_t* Bu2 = smu + N2_OB2;
    uint32_t* T1  = smu + N2_OT1;
    float* sb2 = (float*)(smu + N2_OS2);
    float* slb = (float*)(smu + N2_OSL);
    float* satom = (float*)(smu + N2_OSA);

    const int tid = threadIdx.x, wid = tid >> 5, lane = tid & 31;
    const int half = wid >> 3, w8 = wid & 7;
    const int qr = lane >> 2, qc = lane & 3;

    for (int i = tid; i < 128 * 64; i += 512) {
        int kp = i >> 7, n = i & 127;
        uint32_t hh, ll;
        split2(W2[(2 * kp) * 128 + n], W2[(2 * kp + 1) * 128 + n], hh, ll);
        Bu1[n * 132 + kp] = hh; Bu1[n * 132 + 64 + kp] = ll;
        split2(Wl[(2 * kp) * 128 + n], Wl[(2 * kp + 1) * 128 + n], hh, ll);
        Bu2[n * 132 + kp] = hh; Bu2[n * 132 + 64 + kp] = ll;
    }
    if (tid < 128) { sb2[tid] = b2[tid]; slb[tid] = lb[tid]; }
    __syncthreads();

    const int r0 = w8 * 16 + qr;
    const long base = (long)blockIdx.x * 128;

    // GEMM1: agg @ W2 -> ssp -> T1
    {
        float acc[8][4];
        #pragma unroll
        for (int nb = 0; nb < 8; nb++) { acc[nb][0]=0.f; acc[nb][1]=0.f; acc[nb][2]=0.f; acc[nb][3]=0.f; }
        #pragma unroll
        for (int ks = 0; ks < 8; ks++) {
            const float* xr = agg + (base + r0) * 128 + ks * 16 + 2 * qc;
            float2 v00 = *(const float2*)xr;
            float2 v01 = *(const float2*)(xr + 8);
            float2 v10 = *(const float2*)(xr + 8 * 128);
            float2 v11 = *(const float2*)(xr + 8 * 128 + 8);
            uint32_t aH0,aH1,aH2,aH3,aL0,aL1,aL2,aL3;
            split2(v00.x, v00.y, aH0, aL0);
            split2(v10.x, v10.y, aH1, aL1);
            split2(v01.x, v01.y, aH2, aL2);
            split2(v11.x, v11.y, aH3, aL3);
            #pragma unroll
            for (int nb = 0; nb < 8; nb++) {
                int noff = ((half * 8 + nb) * 8 + qr) * 132 + ks * 8 + qc;
                uint32_t bh0 = Bu1[noff], bh1 = Bu1[noff + 4];
                mma16816(acc[nb], aH0, aH1, aH2, aH3, bh0, bh1);
                mma16816(acc[nb], aL0, aL1, aL2, aL3, bh0, bh1);
                uint32_t bl0 = Bu1[noff + 64], bl1 = Bu1[noff + 68];
                mma16816(acc[nb], aH0, aH1, aH2, aH3, bl0, bl1);
            }
        }
        #pragma unroll
        for (int nb = 0; nb < 8; nb++) {
            int c = (half * 8 + nb) * 8 + 2 * qc;
            int kp = (c >> 1);
            float bx = sb2[c], by = sb2[c + 1];
            uint32_t hh, ll;
            split2(sspf(acc[nb][0] + bx), sspf(acc[nb][1] + by), hh, ll);
            T1[r0 * 132 + kp] = hh; T1[r0 * 132 + 64 + kp] = ll;
            split2(sspf(acc[nb][2] + bx), sspf(acc[nb][3] + by), hh, ll);
            T1[(r0 + 8) * 132 + kp] = hh; T1[(r0 + 8) * 132 + 64 + kp] = ll;
        }
    }
    __syncthreads();

    if (cf1n) {
        for (int i = tid; i < 128 * 64; i += 512) {
            int kp = i >> 7, n = i & 127;
            uint32_t hh, ll;
            split2(cf1n[(2 * kp) * 128 + n], cf1n[(2 * kp + 1) * 128 + n], hh, ll);
            Bu1[n * 132 + kp] = hh; Bu1[n * 132 + 64 + kp] = ll;
        }
    }

    // GEMM2: T1 @ Wl, residual -> h; re-split h_new into T1 (always)
    {
        float acc[8][4];
        #pragma unroll
        for (int nb = 0; nb < 8; nb++) { acc[nb][0]=0.f; acc[nb][1]=0.f; acc[nb][2]=0.f; acc[nb][3]=0.f; }
        #pragma unroll
        for (int ks = 0; ks < 8; ks++) {
            int xo0 = r0 * 132 + ks * 8 + qc;
            int xo1 = (r0 + 8) * 132 + ks * 8 + qc;
            uint32_t aH0 = T1[xo0],      aH1 = T1[xo1];
            uint32_t aH2 = T1[xo0 + 4],  aH3 = T1[xo1 + 4];
            uint32_t aL0 = T1[xo0 + 64], aL1 = T1[xo1 + 64];
            uint32_t aL2 = T1[xo0 + 68], aL3 = T1[xo1 + 68];
            #pragma unroll
            for (int nb = 0; nb < 8; nb++) {
                int noff = ((half * 8 + nb) * 8 + qr) * 132 + ks * 8 + qc;
                uint32_t bh0 = Bu2[noff], bh1 = Bu2[noff + 4];
                mma16816(acc[nb], aH0, aH1, aH2, aH3, bh0, bh1);
                mma16816(acc[nb], aL0, aL1, aL2, aL3, bh0, bh1);
                uint32_t bl0 = Bu2[noff + 64], bl1 = Bu2[noff + 68];
                mma16816(acc[nb], aH0, aH1, aH2, aH3, bl0, bl1);
            }
        }
        #pragma unroll
        for (int nb = 0; nb < 8; nb++) {
            int c = (half * 8 + nb) * 8 + 2 * qc;
            float bx = slb[c], by = slb[c + 1];
            float* y0 = h + (base + r0) * 128 + c;
            float* y1 = h + (base + r0 + 8) * 128 + c;
            float2 p0 = *(float2*)y0, p1 = *(float2*)y1;
            float v0 = p0.x + acc[nb][0] + bx, v1 = p0.y + acc[nb][1] + by;
            float v2 = p1.x + acc[nb][2] + bx, v3 = p1.y + acc[nb][3] + by;
            *(float2*)y0 = make_float2(v0, v1);
            *(float2*)y1 = make_float2(v2, v3);
            int kp = c >> 1;
            uint32_t hh, ll;
            split2(v0, v1, hh, ll);
            T1[r0 * 132 + kp] = hh; T1[r0 * 132 + 64 + kp] = ll;
            split2(v2, v3, hh, ll);
            T1[(r0 + 8) * 132 + kp] = hh; T1[(r0 + 8) * 132 + 64 + kp] = ll;
        }
    }
    __syncthreads();   // T1 (h_new split) complete for all rows

    if (cf1n) {
        // GEMM3: hx = h_new @ cf1n
        float acc[8][4];
        #pragma unroll
        for (int nb = 0; nb < 8; nb++) { acc[nb][0]=0.f; acc[nb][1]=0.f; acc[nb][2]=0.f; acc[nb][3]=0.f; }
        #pragma unroll
        for (int ks = 0; ks < 8; ks++) {
            int xo0 = r0 * 132 + ks * 8 + qc;
            int xo1 = (r0 + 8) * 132 + ks * 8 + qc;
            uint32_t aH0 = T1[xo0],      aH1 = T1[xo1];
            uint32_t aH2 = T1[xo0 + 4],  aH3 = T1[xo1 + 4];
            uint32_t aL0 = T1[xo0 + 64], aL1 = T1[xo1 + 64];
            uint32_t aL2 = T1[xo0 + 68], aL3 = T1[xo1 + 68];
            #pragma unroll
            for (int nb = 0; nb < 8; nb++) {
                int noff = ((half * 8 + nb) * 8 + qr) * 132 + ks * 8 + qc;
                uint32_t bh0 = Bu1[noff], bh1 = Bu1[noff + 4];
                mma16816(acc[nb], aH0, aH1, aH2, aH3, bh0, bh1);
                mma16816(acc[nb], aL0, aL1, aL2, aL3, bh0, bh1);
                uint32_t bl0 = Bu1[noff + 64], bl1 = Bu1[noff + 68];
                mma16816(acc[nb], aH0, aH1, aH2, aH3, bl0, bl1);
            }
        }
        #pragma unroll
        for (int nb = 0; nb < 8; nb++) {
            int c = (half * 8 + nb) * 8 + 2 * qc;
            *(float2*)(hx + (base + r0) * 128 + c)     = make_float2(acc[nb][0], acc[nb][1]);
            *(float2*)(hx + (base + r0 + 8) * 128 + c) = make_float2(acc[nb][2], acc[nb][3]);
        }
        return;
    }

    // ---- Fused output head (last layer) ----
    for (int i = tid; i < 64 * 64; i += 512) {
        int kp = i >> 6, n = i & 63;
        uint32_t hh, ll;
        split2(o1w[(2 * kp) * 64 + n], o1w[(2 * kp + 1) * 64 + n], hh, ll);
        Bu1[n * 132 + kp] = hh; Bu1[n * 132 + 64 + kp] = ll;
    }
    if (tid < 64) { sb2[tid] = o1b[tid]; slb[tid] = o2w[tid]; }
    if (tid < 128) satom[tid] = 0.f;
    __syncthreads();

    {
        float acc[4][4];
        #pragma unroll
        for (int nb = 0; nb < 4; nb++) { acc[nb][0]=0.f; acc[nb][1]=0.f; acc[nb][2]=0.f; acc[nb][3]=0.f; }
        #pragma unroll
        for (int ks = 0; ks < 8; ks++) {
            int xo0 = r0 * 132 + ks * 8 + qc;
            int xo1 = (r0 + 8) * 132 + ks * 8 + qc;
            uint32_t aH0 = T1[xo0],      aH1 = T1[xo1];
            uint32_t aH2 = T1[xo0 + 4],  aH3 = T1[xo1 + 4];
            uint32_t aL0 = T1[xo0 + 64], aL1 = T1[xo1 + 64];
            uint32_t aL2 = T1[xo0 + 68], aL3 = T1[xo1 + 68];
            #pragma unroll
            for (int nb = 0; nb < 4; nb++) {
                int cb2 = half * 4 + nb;
                int noff = (cb2 * 8 + qr) * 132 + ks * 8 + qc;
                uint32_t bh0 = Bu1[noff], bh1 = Bu1[noff + 4];
                mma16816(acc[nb], aH0, aH1, aH2, aH3, bh0, bh1);
                mma16816(acc[nb], aL0, aL1, aL2, aL3, bh0, bh1);
                uint32_t bl0 = Bu1[noff + 64], bl1 = Bu1[noff + 68];
                mma16816(acc[nb], aH0, aH1, aH2, aH3, bl0, bl1);
            }
        }
        float P0 = 0.f, P1 = 0.f;
        #pragma unroll
        for (int nb = 0; nb < 4; nb++) {
            int c = (half * 4 + nb) * 8 + 2 * qc;
            float bx = sb2[c], by = sb2[c + 1];
            float wx = slb[c], wy = slb[c + 1];
            P0 += sspf(acc[nb][0] + bx) * wx + sspf(acc[nb][1] + by) * wy;
            P1 += sspf(acc[nb][2] + bx) * wx + sspf(acc[nb][3] + by) * wy;
        }
        atomicAdd(&satom[r0], P0);
        atomicAdd(&satom[r0 + 8], P1);
    }
    __syncthreads();

    if (tid < 4) {
        float s = 0.f;
        #pragma unroll
        for (int a = 0; a < 32; a++) s += satom[tid * 32 + a];
        out[blockIdx.x * 4 + tid] = s + 32.f * o2b[0];
    }
}

// ---------------------------------------------------------------------------
// Table builder, N-split (unchanged)
// ---------------------------------------------------------------------------
#define BLD_SMEM (34304 * 4)

__global__ __launch_bounds__(512, 1)
void k_build(const float* __restrict__ w1all, const float* __restrict__ b1all,
             const float* __restrict__ w2all, const float* __restrict__ b2all)
{
    extern __shared__ uint32_t smu[];
    uint32_t* B1u = smu;
    uint32_t* B2u = smu + 8704;
    uint32_t* T1  = smu + 17152;
    float* sb1 = (float*)(smu + 34048);
    float* sb2 = (float*)(smu + 34176);

    const int tpl = TAB_N / 128;
    const int ch = blockIdx.x & 1;
    const int t  = (blockIdx.x >> 1) % tpl;
    const int l  = (blockIdx.x >> 1) / tpl;
    const float* w1 = w1all + (long)l * GDIM * HDIM;
    const float* b1 = b1all + (long)l * HDIM;
    const float* w2 = w2all + (long)l * HDIM * HDIM;
    const float* b2 = b2all + (long)l * HDIM;

    const int tid = threadIdx.x, wid = tid >> 5, lane = tid & 31;
    const int half = wid >> 3, w8 = wid & 7;
    const int qr = lane >> 2, qc = lane & 3;

    for (int i = tid; i < 128 * 32; i += 512) {
        int kp = i >> 7, n = i & 127, k = 2 * kp;
        float v0 = (k < GDIM)     ? w1[k * 128 + n]       : 0.f;
        float v1 = (k + 1 < GDIM) ? w1[(k + 1) * 128 + n] : 0.f;
        uint32_t h, lv; split2(v0, v1, h, lv);
        B1u[n * 68 + kp] = h;
        B1u[n * 68 + 32 + kp] = lv;
    }
    for (int i = tid; i < 64 * 64; i += 512) {
        int kp = i >> 6, nl = i & 63;
        int n = ch * 64 + nl;
        uint32_t h, lv;
        split2(w2[(2 * kp) * 128 + n], w2[(2 * kp + 1) * 128 + n], h, lv);
        B2u[nl * 132 + kp] = h;
        B2u[nl * 132 + 64 + kp] = lv;
    }
    if (tid < 128) { sb1[tid] = b1[tid]; sb2[tid] = b2[tid]; }
    __syncthreads();

    const float step  = CUTOFF / (GDIM - 1);
    const float coeff = -0.5f / (step * step);
    const float PIOC  = 3.14159265358979f / CUTOFF;
    const float DELTA = CUTOFF / (float)TAB_N;
    const int r0 = w8 * 16 + qr;

    float dv0 = (float)(t * 128 + r0) * DELTA;
    float dv1 = (float)(t * 128 + r0 + 8) * DELTA;

    uint32_t aH[4][4], aL[4][4];
    #pragma unroll
    for (int ks = 0; ks < 4; ks++) {
        float g0 = (float)(ks * 16 + 2 * qc) * step;
        eaf(dv0, g0,            step, coeff, aH[ks][0], aL[ks][0]);
        eaf(dv1, g0,            step, coeff, aH[ks][1], aL[ks][1]);
        eaf(dv0, g0 + 8.f*step, step, coeff, aH[ks][2], aL[ks][2]);
        eaf(dv1, g0 + 8.f*step, step, coeff, aH[ks][3], aL[ks][3]);
    }

    #pragma unroll
    for (int nb = 0; nb < 8; nb++) {
        float acc[4] = {0.f, 0.f, 0.f, 0.f};
        #pragma unroll
        for (int ks = 0; ks < 4; ks++) {
            int noff = ((half * 8 + nb) * 8 + qr) * 68 + ks * 8 + qc;
            uint32_t bh0 = B1u[noff], bh1 = B1u[noff + 4];
            mma16816(acc, aH[ks][0], aH[ks][1], aH[ks][2], aH[ks][3], bh0, bh1);
            mma16816(acc, aL[ks][0], aL[ks][1], aL[ks][2], aL[ks][3], bh0, bh1);
            uint32_t bl0 = B1u[noff + 32], bl1 = B1u[noff + 36];
            mma16816(acc, aH[ks][0], aH[ks][1], aH[ks][2], aH[ks][3], bl0, bl1);
        }
        int c = (half * 8 + nb) * 8 + 2 * qc;
        int kp = c >> 1;
        float bx = sb1[c], by = sb1[c + 1];
        uint32_t hh, ll;
        split2(sspf(acc[0] + bx), sspf(acc[1] + by), hh, ll);
        T1[r0 * 132 + kp] = hh; T1[r0 * 132 + 64 + kp] = ll;
        split2(sspf(acc[2] + bx), sspf(acc[3] + by), hh, ll);
        T1[(r0 + 8) * 132 + kp] = hh; T1[(r0 + 8) * 132 + 64 + kp] = ll;
    }
    __syncthreads();

    float acc2[4][4];
    #pragma unroll
    for (int nb = 0; nb < 4; nb++) { acc2[nb][0]=0.f; acc2[nb][1]=0.f; acc2[nb][2]=0.f; acc2[nb][3]=0.f; }
    #pragma unroll
    for (int ks = 0; ks < 8; ks++) {
        int xo0 = r0 * 132 + ks * 8 + qc;
        int xo1 = (r0 + 8) * 132 + ks * 8 + qc;
        uint32_t aH0 = T1[xo0],      aH1 = T1[xo1];
        uint32_t aH2 = T1[xo0 + 4],  aH3 = T1[xo1 + 4];
        uint32_t aL0 = T1[xo0 + 64], aL1 = T1[xo1 + 64];
        uint32_t aL2 = T1[xo0 + 68], aL3 = T1[xo1 + 68];
        #pragma unroll
        for (int nb = 0; nb < 4; nb++) {
            int cb2 = half * 4 + nb;
            int noff = (cb2 * 8 + qr) * 132 + ks * 8 + qc;
            uint32_t bh0 = B2u[noff], bh1 = B2u[noff + 4];
            mma16816(acc2[nb], aH0, aH1, aH2, aH3, bh0, bh1);
            mma16816(acc2[nb], aL0, aL1, aL2, aL3, bh0, bh1);
            uint32_t bl0 = B2u[noff + 64], bl1 = B2u[noff + 68];
            mma16816(acc2[nb], aH0, aH1, aH2, aH3, bl0, bl1);
        }
    }

    float cc0 = 0.5f * (cosf(dv0 * PIOC) + 1.f);
    float cc1 = 0.5f * (cosf(dv1 * PIOC) + 1.f);
    float* trow = g_wtab + ((long)l * (TAB_N + 1) + t * 128 + r0) * 128;
    #pragma unroll
    for (int nb = 0; nb < 4; nb++) {
        int c = ch * 64 + (half * 4 + nb) * 8 + 2 * qc;
        float bx = sb2[c], by = sb2[c + 1];
        *(float2*)(trow + c) =
            make_float2((acc2[nb][0] + bx) * cc0, (acc2[nb][1] + by) * cc0);
        *(float2*)(trow + 8 * 128 + c) =
            make_float2((acc2[nb][2] + bx) * cc1, (acc2[nb][3] + by) * cc1);
    }
    if (t == 0 && ch == 0 && tid < 128)
        g_wtab[((long)l * (TAB_N + 1) + TAB_N) * 128 + tid] = 0.f;
}

// ---------------------------------------------------------------------------
// Edge-centric table-lookup kernel: CTA = (molecule, 64-col half), 8 warps.
// One warp per edge (strided); lane owns columns {lane, lane+32} (stride-1,
// conflict-free SMEM atomics and loads). No syncs in main loop.
// ---------------------------------------------------------------------------
__global__ __launch_bounds__(256)
void k_edge_tab(const float* __restrict__ pos, const float* __restrict__ wtab)
{
    __shared__ float hxs [APM * 68];
    __shared__ float sagg[APM * 68];
    __shared__ float ps[96];

    const int tid = threadIdx.x, wid = tid >> 5, lane = tid & 31;
    const int m = blockIdx.x >> 1, ch = blockIdx.x & 1;
    const int cb = ch * 64;
    const float SCALE = (float)TAB_N / CUTOFF;

    const int nu = g_ucnt[m];

    for (int i = tid; i < APM * 64; i += 256) {
        int a = i >> 6, c = i & 63;
        hxs[a * 68 + c] = g_hx[(long)(m * APM + a) * 128 + cb + c];
        sagg[a * 68 + c] = 0.f;
    }
    if (tid < 96) ps[tid] = pos[m * 96 + tid];
    __syncthreads();

    const float* tabc = wtab + cb + lane;   // cols lane and lane+32

    for (int e = wid; e < nu; e += 8) {
        unsigned pk = g_upak[m * 512 + e];        // broadcast load
        int il = (int)(pk >> 8), jl = (int)(pk & 255);
        float dx = ps[3*il]   - ps[3*jl];
        float dy = ps[3*il+1] - ps[3*jl+1];
        float dz = ps[3*il+2] - ps[3*jl+2];
        float d = sqrtf(dx*dx + dy*dy + dz*dz);
        float tt = d * SCALE;
        int i0 = (int)tt;
        i0 = (i0 > TAB_N - 1) ? (TAB_N - 1) : i0;
        float f = tt - (float)i0;
        const float* T = tabc + (long)i0 * 128;
        float wa0 = T[0],   wb0 = T[128];
        float wa1 = T[32],  wb1 = T[160];
        float w0 = wa0 + f * (wb0 - wa0);
        float w1 = wa1 + f * (wb1 - wa1);
        float hj0 = hxs[jl * 68 + lane],      hj1 = hxs[jl * 68 + 32 + lane];
        float hi0 = hxs[il * 68 + lane],      hi1 = hxs[il * 68 + 32 + lane];
        atomicAdd(&sagg[il * 68 + lane],      w0 * hj0);
        atomicAdd(&sagg[il * 68 + 32 + lane], w1 * hj1);
        atomicAdd(&sagg[jl * 68 + lane],      w0 * hi0);
        atomicAdd(&sagg[jl * 68 + 32 + lane], w1 * hi1);
    }
    __syncthreads();

    for (int i = tid; i < APM * 64; i += 256) {
        int a = i >> 6, c = i & 63;
        g_agg[(long)(m * APM + a) * 128 + cb + c] = sagg[a * 68 + c];
    }
}

// ---------------------------------------------------------------------------
extern "C" void kernel_launch(void* const* d_in, const int* in_sizes, int n_in,
                              void* d_out, int out_size)
{
    const int*   z       = (const int*)  d_in[0];
    const float* pos     = (const float*)d_in[1];
    const int*   ei      = (const int*)  d_in[3];
    const float* emb     = (const float*)d_in[4];
    const float* mlp_w1  = (const float*)d_in[5];
    const float* mlp_b1  = (const float*)d_in[6];
    const float* mlp_w2  = (const float*)d_in[7];
    const float* mlp_b2  = (const float*)d_in[8];
    const float* cf1_w   = (const float*)d_in[9];
    const float* cf2_w   = (const float*)d_in[10];
    const float* cf2_b   = (const float*)d_in[11];
    const float* lin_w   = (const float*)d_in[12];
    const float* lin_b   = (const float*)d_in[13];
    const float* out1_w  = (const float*)d_in[14];
    const float* out1_b  = (const float*)d_in[15];
    const float* out2_w  = (const float*)d_in[16];
    const float* out2_b  = (const float*)d_in[17];

    int E = in_sizes[3] / 2;
    const int* src = ei;
    const int* dst = ei + E;

    cudaFuncSetAttribute(k_build, cudaFuncAttributeMaxDynamicSharedMemorySize, BLD_SMEM);
    cudaFuncSetAttribute(k_n1e, cudaFuncAttributeMaxDynamicSharedMemorySize, N1_SMEM);
    cudaFuncSetAttribute(k_n2x, cudaFuncAttributeMaxDynamicSharedMemorySize, N2_SMEM);

    float *ph, *phx, *pagg, *ptab;
    cudaGetSymbolAddress((void**)&ph,   g_h);
    cudaGetSymbolAddress((void**)&phx,  g_hx);
    cudaGetSymbolAddress((void**)&pagg, g_agg);
    cudaGetSymbolAddress((void**)&ptab, g_wtab);

    float* out = (float*)d_out;

    k_prep<<<NMOL, 128>>>(src, dst, E);
    k_build<<<LINT * (TAB_N / 128) * 2, 512, BLD_SMEM>>>(mlp_w1, mlp_b1, mlp_w2, mlp_b2);
    k_n1e<<<128, 512, N1_SMEM>>>(z, emb, cf1_w, ph, phx);

    for (int l = 0; l < LINT; l++) {
        k_edge_tab<<<NMOL * 2, 256>>>(pos, ptab + (long)l * (TAB_N + 1) * HDIM);
        const float* cf1n = (l + 1 < LINT) ? (cf1_w + (long)(l + 1) * HDIM * HDIM) : nullptr;
        k_n2x<<<128, 512, N2_SMEM>>>(
            pagg, cf2_w + (long)l*HDIM*HDIM, cf2_b + (long)l*HDIM,
            lin_w + (long)l*HDIM*HDIM, lin_b + (long)l*HDIM, ph,
            cf1n, phx,
            out1_w, out1_b, out2_w, out2_b, out);
    }
}